// round 13
// baseline (speedup 1.0000x reference)
#include <cuda_runtime.h>
#include <cuda_fp16.h>
#include <stdint.h>

#define BB   512
#define TT   256
#define HHID 512
#define HOR  64
#define NCTA 128
#define NGRP 32                         /* CTAs per independent batch group */
#define NTHR 320                        /* 8 consumer warps + 2 producer warps */
#define NCON 256
#define WS_BYTES    65536               /* one matrix slice: 64 rows x 512 halves */
#define RING_OFF    (3 * WS_BYTES)      /* 196608 */
#define STAGE_BYTES 8192                /* K=32 chunk: 128 rows folded to 64x128B */
#define NBUF 4
#define DINS_OFF    (RING_OFF + NBUF * STAGE_BYTES)   /* 229376 */
#define MBAR_OFF    (DINS_OFF + 512)                  /* 229888 */
#define SMEM_BYTES  (MBAR_OFF + 128)                  /* 230016 */

__device__ __align__(128) __half g_h0[2][BB * HHID];
__device__ __align__(128) __half g_h1[2][BB * HHID];
__device__ float  g_part2[BB * 64];     /* [row][slot], slot = nc*2 + (warp&1) */
__device__ unsigned g_count0 = 0u;              /* init barrier (global) */
__device__ volatile unsigned g_gen0v = 0u;
__device__ unsigned g_count4[4] = {0u, 0u, 0u, 0u};   /* decoder mid bars */
__device__ volatile unsigned g_gen4[4] = {0u, 0u, 0u, 0u};
/* dataflow flags: gfA[g][nc] = #A-pointwises done by CTA (g,nc); gfB likewise */
__device__ volatile unsigned gfA[4][NGRP];
__device__ volatile unsigned gfB[4][NGRP];

/* ---------- barriers ---------- */
__device__ __forceinline__ void grid_bar_full() {      // ALL CTAs, init only
    __syncthreads();
    __threadfence();
    if (threadIdx.x == 0) {
        unsigned g = g_gen0v;
        if (atomicAdd(&g_count0, 1u) == NCTA - 1) {
            g_count0 = 0u; __threadfence(); g_gen0v = g + 1u;
        } else { while (g_gen0v == g) { } }
        __threadfence();
    }
    __syncthreads();
}
#define CBAR() asm volatile("bar.sync 1, %0;" :: "n"(NCON) : "memory")
__device__ __forceinline__ void group_bar_c(int tid, int grp_id) {  // consumers, own group
    CBAR();
    __threadfence();
    if (tid == 0) {
        unsigned g = g_gen4[grp_id];
        if (atomicAdd(&g_count4[grp_id], 1u) == NGRP - 1) {
            g_count4[grp_id] = 0u; __threadfence(); g_gen4[grp_id] = g + 1u;
        } else { while (g_gen4[grp_id] == g) { } }
        __threadfence();
    }
    CBAR();
}

/* ---------- mbarrier ---------- */
__device__ __forceinline__ void mb_init(uint32_t a, uint32_t cnt) {
    asm volatile("mbarrier.init.shared.b64 [%0], %1;" :: "r"(a), "r"(cnt) : "memory");
}
__device__ __forceinline__ void mb_arrive(uint32_t a) {
    asm volatile("mbarrier.arrive.shared.b64 _, [%0];" :: "r"(a) : "memory");
}
__device__ __forceinline__ void mb_wait(uint32_t a, uint32_t par) {
    asm volatile(
        "{\n\t.reg .pred P;\n\t"
        "LW_%=:\n\t"
        "mbarrier.try_wait.parity.acquire.cta.shared::cta.b64 P, [%0], %1, 0x989680;\n\t"
        "@P bra.uni LD_%=;\n\t"
        "bra.uni LW_%=;\n\t"
        "LD_%=:\n\t}"
        :: "r"(a), "r"(par) : "memory");
}

/* ---------- async copy / mma ---------- */
__device__ __forceinline__ void cpa16(uint32_t dst, const void* src) {
    asm volatile("cp.async.cg.shared.global [%0], [%1], 16;\n" :: "r"(dst), "l"(src));
}
__device__ __forceinline__ void ldsm4(uint32_t* r, uint32_t a) {
    asm volatile("ldmatrix.sync.aligned.m8n8.x4.shared.b16 {%0,%1,%2,%3}, [%4];\n"
                 : "=r"(r[0]), "=r"(r[1]), "=r"(r[2]), "=r"(r[3]) : "r"(a));
}
#define MMA(d, A, B0, B1)                                                      \
    asm volatile("mma.sync.aligned.m16n8k16.row.col.f32.f16.f16.f32 "          \
                 "{%0,%1,%2,%3},{%4,%5,%6,%7},{%8,%9},{%0,%1,%2,%3};"          \
                 : "+f"(d[0]), "+f"(d[1]), "+f"(d[2]), "+f"(d[3])              \
                 : "r"(A[0]), "r"(A[1]), "r"(A[2]), "r"(A[3]), "r"(B0), "r"(B1))

/* producer: stage one K=32 chunk (128 rows x 32 halves) with 1 warp */
__device__ __forceinline__ void p_stage(uint32_t ring, int buf, const __half* hsrc,
                                        int b0, int kc, int lane, uint32_t fullbar) {
    uint32_t base = ring + buf * STAGE_BYTES;
#pragma unroll
    for (int u = 0; u < 16; u++) {
        int i = lane + u * 32;              // 0..511 16B blocks
        int br = i >> 2, cb4 = i & 3;
        int phys = (cb4 + ((br >> 6) << 2)) ^ (br & 7);
        cpa16(base + (br & 63) * 128 + (phys << 4),
              hsrc + (size_t)(b0 + br) * HHID + kc + cb4 * 8);
    }
    asm volatile("cp.async.mbarrier.arrive.noinc.shared.b64 [%0];" :: "r"(fullbar) : "memory");
}

/* dual chunk, 32x32 tile: accA += A x W0^T, accB += A x W1^T (shared A frags) */
__device__ __forceinline__ void chunk_dual32(float aA[2][4][4], float aB[2][4][4],
                                             uint32_t Ast, uint32_t W0, uint32_t W1,
                                             int chk, int wm, int wn, int lane) {
    const int a_row = lane & 15, akc = lane >> 4;
    const int b_row = (lane & 7) + ((lane >> 4) << 3), bkc = (lane >> 3) & 1;
    const int R0 = wn + b_row, R1 = R0 + 16;
    const int R07 = R0 & 7, R17 = R1 & 7;
    const uint32_t W0r0 = W0 + R0 * 1024, W0r1 = W0 + R1 * 1024;
    const uint32_t W1r0 = W1 + R0 * 1024, W1r1 = W1 + R1 * 1024;
    const int lr0 = wm + a_row, lr1 = lr0 + 16;
    const uint32_t Ar0 = Ast + (lr0 & 63) * 128, Ar1 = Ast + (lr1 & 63) * 128;
    const int hb0 = (lr0 >> 6) << 2, hb1 = (lr1 >> 6) << 2;
    const int l07 = lr0 & 7, l17 = lr1 & 7;
#pragma unroll
    for (int kk = 0; kk < 32; kk += 16) {
        int k8 = kk >> 3;
        int cb = chk * 4 + k8 + bkc;
        uint32_t Ca[4], Cb[4], Ba[4], Bb[4], A0[4], A1[4];
        ldsm4(Ca, W0r0 + ((cb ^ R07) << 4));
        ldsm4(Cb, W0r1 + ((cb ^ R17) << 4));
        ldsm4(Ba, W1r0 + ((cb ^ R07) << 4));
        ldsm4(Bb, W1r1 + ((cb ^ R17) << 4));
        ldsm4(A0, Ar0 + ((((k8 + akc + hb0) ^ l07)) << 4));
        ldsm4(A1, Ar1 + ((((k8 + akc + hb1) ^ l17)) << 4));
        MMA(aB[0][0], A0, Ba[0], Ba[1]);
        MMA(aB[0][1], A0, Ba[2], Ba[3]);
        MMA(aB[0][2], A0, Bb[0], Bb[1]);
        MMA(aB[0][3], A0, Bb[2], Bb[3]);
        MMA(aB[1][0], A1, Ba[0], Ba[1]);
        MMA(aB[1][1], A1, Ba[2], Ba[3]);
        MMA(aB[1][2], A1, Bb[0], Bb[1]);
        MMA(aB[1][3], A1, Bb[2], Bb[3]);
        MMA(aA[0][0], A0, Ca[0], Ca[1]);
        MMA(aA[0][1], A0, Ca[2], Ca[3]);
        MMA(aA[0][2], A0, Cb[0], Cb[1]);
        MMA(aA[0][3], A0, Cb[2], Cb[3]);
        MMA(aA[1][0], A1, Ca[0], Ca[1]);
        MMA(aA[1][1], A1, Ca[2], Ca[3]);
        MMA(aA[1][2], A1, Cb[0], Cb[1]);
        MMA(aA[1][3], A1, Cb[2], Cb[3]);
    }
}

/* single chunk, 32x32 tile: accB += A x W^T */
__device__ __forceinline__ void chunk_one32(float aB[2][4][4],
                                            uint32_t Ast, uint32_t W1,
                                            int chk, int wm, int wn, int lane) {
    const int a_row = lane & 15, akc = lane >> 4;
    const int b_row = (lane & 7) + ((lane >> 4) << 3), bkc = (lane >> 3) & 1;
    const int R0 = wn + b_row, R1 = R0 + 16;
    const int R07 = R0 & 7, R17 = R1 & 7;
    const uint32_t W1r0 = W1 + R0 * 1024, W1r1 = W1 + R1 * 1024;
    const int lr0 = wm + a_row, lr1 = lr0 + 16;
    const uint32_t Ar0 = Ast + (lr0 & 63) * 128, Ar1 = Ast + (lr1 & 63) * 128;
    const int hb0 = (lr0 >> 6) << 2, hb1 = (lr1 >> 6) << 2;
    const int l07 = lr0 & 7, l17 = lr1 & 7;
#pragma unroll
    for (int kk = 0; kk < 32; kk += 16) {
        int k8 = kk >> 3;
        int cb = chk * 4 + k8 + bkc;
        uint32_t Ba[4], Bb[4], A0[4], A1[4];
        ldsm4(Ba, W1r0 + ((cb ^ R07) << 4));
        ldsm4(Bb, W1r1 + ((cb ^ R17) << 4));
        ldsm4(A0, Ar0 + ((((k8 + akc + hb0) ^ l07)) << 4));
        ldsm4(A1, Ar1 + ((((k8 + akc + hb1) ^ l17)) << 4));
        MMA(aB[0][0], A0, Ba[0], Ba[1]);
        MMA(aB[0][1], A0, Ba[2], Ba[3]);
        MMA(aB[0][2], A0, Bb[0], Bb[1]);
        MMA(aB[0][3], A0, Bb[2], Bb[3]);
        MMA(aB[1][0], A1, Ba[0], Ba[1]);
        MMA(aB[1][1], A1, Ba[2], Ba[3]);
        MMA(aB[1][2], A1, Bb[0], Bb[1]);
        MMA(aB[1][3], A1, Bb[2], Bb[3]);
    }
}

/* convert ONE weight matrix 64-row slice fp32 -> fp16 into swizzled smem slot */
__device__ void load_w1(char* smem, const float* W, int moff, int n0, int tid, int nthr) {
    for (int i = tid; i < 64 * 512; i += nthr) {
        int r = i >> 9, k = i & 511;
        int pr = n0 + r, j = pr >> 2, g = pr & 3;
        float v = W[(size_t)(g * 512 + j) * HHID + k];
        int ck = k >> 3;
        int off = moff + r * 1024 + (((ck ^ (r & 7)) << 4)) + (k & 7) * 2;
        *(__half*)(smem + off) = __float2half(v);
    }
}

__device__ __forceinline__ void load_gv(float d[2][4], const float* b, int u0, int u1) {
    d[0][0] = b[u0]; d[0][1] = b[512 + u0]; d[0][2] = b[1024 + u0]; d[0][3] = b[1536 + u0];
    d[1][0] = b[u1]; d[1][1] = b[512 + u1]; d[1][2] = b[1024 + u1]; d[1][3] = b[1536 + u1];
}

/* HW tanh (sm_75+): max abs err ~6e-4, within budget (verified R11/R12) */
__device__ __forceinline__ float tanhap(float z) {
    float r;
    asm("tanh.approx.f32 %0, %1;" : "=f"(r) : "f"(z));
    return r;
}
__device__ __forceinline__ float sigf(float z) { return 0.5f * tanhap(0.5f * z) + 0.5f; }

/* balanced in-register LSTM pointwise for 32x32 tiles (verified layout) */
__device__ __forceinline__ void pointwise_frag(
    const float acc[2][4][4], float* cst /*[8]*/,
    const float bv[2][4], const float wv[2][4], bool use_w,
    const float* dins, int wm, int grp, int tig,
    __half* hout, int b0, const int* ug,
    bool do_head, const float* hw, int slot) {
    const unsigned FULL = 0xFFFFFFFFu;
    float pv[4] = {0.f, 0.f, 0.f, 0.f};
#pragma unroll
    for (int mf = 0; mf < 2; mf++) {
        int r0 = wm + mf * 16 + grp;
        float va = use_w ? dins[r0] : 0.f;
        float vb = use_w ? dins[r0 + 8] : 0.f;
#pragma unroll
        for (int nf = 0; nf < 4; nf++) {
            float e0 = __shfl_xor_sync(FULL, acc[mf][nf][0], 1);
            float e1 = __shfl_xor_sync(FULL, acc[mf][nf][1], 1);
            float e2 = __shfl_xor_sync(FULL, acc[mf][nf][2], 1);
            float e3 = __shfl_xor_sync(FULL, acc[mf][nf][3], 1);
            if (((nf ^ tig) & 1) == 0) {
                int no = nf >> 1;
                float zi0, zf0, zg0, zo0, zi1, zf1, zg1, zo1;
                if ((tig & 1) == 0) {
                    zi0 = acc[mf][nf][0]; zf0 = acc[mf][nf][1]; zg0 = e0; zo0 = e1;
                    zi1 = acc[mf][nf][2]; zf1 = acc[mf][nf][3]; zg1 = e2; zo1 = e3;
                } else {
                    zg0 = acc[mf][nf][0]; zo0 = acc[mf][nf][1]; zi0 = e0; zf0 = e1;
                    zg1 = acc[mf][nf][2]; zo1 = acc[mf][nf][3]; zi1 = e2; zf1 = e3;
                }
                zi0 += bv[no][0]; zf0 += bv[no][1]; zg0 += bv[no][2]; zo0 += bv[no][3];
                zi1 += bv[no][0]; zf1 += bv[no][1]; zg1 += bv[no][2]; zo1 += bv[no][3];
                if (use_w) {
                    zi0 += va * wv[no][0]; zf0 += va * wv[no][1];
                    zg0 += va * wv[no][2]; zo0 += va * wv[no][3];
                    zi1 += vb * wv[no][0]; zf1 += vb * wv[no][1];
                    zg1 += vb * wv[no][2]; zo1 += vb * wv[no][3];
                }
                int ci = mf * 4 + no * 2;
                float cA = sigf(zf0) * cst[ci]     + sigf(zi0) * tanhap(zg0);
                float cB = sigf(zf1) * cst[ci + 1] + sigf(zi1) * tanhap(zg1);
                cst[ci] = cA; cst[ci + 1] = cB;
                float hA = sigf(zo0) * tanhap(cA);
                float hB = sigf(zo1) * tanhap(cB);
                hout[(size_t)(b0 + r0) * HHID + ug[no]]     = __float2half(hA);
                hout[(size_t)(b0 + r0 + 8) * HHID + ug[no]] = __float2half(hB);
                if (do_head) {
                    pv[mf * 2]     += hA * hw[no];
                    pv[mf * 2 + 1] += hB * hw[no];
                }
            }
        }
    }
    if (do_head) {
#pragma unroll
        for (int q = 0; q < 4; q++) {
            float sv = pv[q] + __shfl_xor_sync(FULL, pv[q], 1);
            sv += __shfl_xor_sync(FULL, sv, 2);
            if (tig == 0) {
                int row = wm + (q >> 1) * 16 + grp + (q & 1) * 8;
                g_part2[(size_t)(b0 + row) * 64 + slot] = sv;
            }
        }
    }
}

__global__ void __launch_bounds__(NTHR, 1)
lstm_persistent_kernel(const float* __restrict__ x,
                       const float* __restrict__ eWih0, const float* __restrict__ eWhh0,
                       const float* __restrict__ eb0,
                       const float* __restrict__ eWih1, const float* __restrict__ eWhh1,
                       const float* __restrict__ eb1,
                       const float* __restrict__ dWih0, const float* __restrict__ dWhh0,
                       const float* __restrict__ db0,
                       const float* __restrict__ dWih1, const float* __restrict__ dWhh1,
                       const float* __restrict__ db1,
                       const float* __restrict__ headW, const float* __restrict__ headb,
                       float* __restrict__ out) {
    extern __shared__ __align__(1024) char smem[];
    uint32_t sb;
    asm("{ .reg .u64 t; cvta.to.shared.u64 t, %1; cvt.u32.u64 %0, t; }"
        : "=r"(sb) : "l"(smem));
    const uint32_t ws0 = sb, ws1 = sb + WS_BYTES, ws2 = sb + 2 * WS_BYTES;
    const uint32_t ring = sb + RING_OFF;
    float* dins = (float*)(smem + DINS_OFF);
    const uint32_t mb = sb + MBAR_OFF;      // full[s]=mb+16s, empty[s]=mb+16s+8

    const int tid  = threadIdx.x;
    const int lane = tid & 31, warp = tid >> 5;
    const int cta  = blockIdx.x;
    const int mbk  = cta >> 5, nc = cta & 31;
    const int b0   = mbk * 128, n0 = nc * 64;
    const int wm   = ((warp & 7) >> 1) * 32, wn = (warp & 1) * 32;
    const int grp  = lane >> 2, tig = lane & 3;
    const int slot = nc * 2 + (warp & 1);
    const unsigned FULL = 0xFFFFFFFFu;

    int ug[2];
    ug[0] = nc * 16 + (wn >> 2) + ((tig & 1) ? 2 : 0) + (tig >> 1);
    ug[1] = ug[0] + 4;

    /* launch-idempotent snapshots of persistent flag counters (taken BEFORE
       the global init barrier; no flag is written until after that barrier) */
    const unsigned snapA = gfA[mbk][lane];
    const unsigned snapB = gfB[mbk][lane];
    unsigned myA0 = 0, myB0 = 0;
    if (tid == 0) { myA0 = gfA[mbk][nc]; myB0 = gfB[mbk][nc]; }

    /* ---- init ---- */
    if (tid == 0) {
#pragma unroll
        for (int s = 0; s < NBUF; s++) {
            mb_init(mb + s * 16, 32);       // full: 32 producer-lane arrivals
            mb_init(mb + s * 16 + 8, 8);    // empty: 8 consumer-warp arrivals
        }
    }
    load_w1(smem, eWhh0, 0, n0, tid, NTHR);
    load_w1(smem, eWih1, WS_BYTES, n0, tid, NTHR);
    load_w1(smem, eWhh1, 2 * WS_BYTES, n0, tid, NTHR);
    {
        int gtid = cta * NTHR + tid;
        for (int i = gtid; i < BB * HHID; i += NCTA * NTHR)
            g_h1[1][i] = __float2half(0.f);   // h1(-1) = 0
    }
    float bv0[2][4], wv0[2][4], bv1[2][4], hw[2];
    load_gv(bv0, eb0, ug[0], ug[1]);
    load_gv(wv0, eWih0, ug[0], ug[1]);
    load_gv(bv1, eb1, ug[0], ug[1]);
    hw[0] = headW[ug[0]]; hw[1] = headW[ug[1]];
    const float hb = headb[0];
    float c0st[8], c1st[8];
#pragma unroll
    for (int i = 0; i < 8; i++) { c0st[i] = 0.f; c1st[i] = 0.f; }

    grid_bar_full();   // publishes zeros + mbarrier inits; no flags written yet

    if (warp >= 8) {
        /* =================== PRODUCER WARPS (8, 9) =================== */
        const int pidx = warp - 8;          // handles chunks with (t & 1) == pidx
        int ph[2] = {1, 1};
        int sl = 0;
        unsigned curA = 0, curB = 0;        // lane-cached relative flag values
#pragma unroll 1
        for (int s = 0; s < TT + HOR; s++) {
            const __half* h0s = g_h0[s & 1];
            const __half* h1p = g_h1[(s & 1) ^ 1];
#pragma unroll 1
            for (int t = pidx; t < 32; t += 2) {
                /* fine-grained dataflow gate: chunk t needs CTAs 2c, 2c+1 */
                if (t < 16) {
                    const unsigned tgt = (unsigned)(s + 1);
                    while (true) {
                        unsigned v0 = __shfl_sync(FULL, curA, 2 * t);
                        unsigned v1 = __shfl_sync(FULL, curA, 2 * t + 1);
                        if (v0 >= tgt && v1 >= tgt) break;
                        curA = (unsigned)(gfA[mbk][lane] - snapA);
                    }
                } else {
                    const int c = t - 16;
                    const unsigned tgt = (unsigned)s;
                    while (true) {
                        unsigned v0 = __shfl_sync(FULL, curB, 2 * c);
                        unsigned v1 = __shfl_sync(FULL, curB, 2 * c + 1);
                        if (v0 >= tgt && v1 >= tgt) break;
                        curB = (unsigned)(gfB[mbk][lane] - snapB);
                    }
                }
                __threadfence();
                int buf = (sl == 0) ? pidx : (pidx + 2);
                mb_wait(mb + buf * 16 + 8, (uint32_t)ph[sl]);
                if (t < 16)
                    p_stage(ring, buf, h0s, b0, t * 32, lane, mb + buf * 16);
                else
                    p_stage(ring, buf, h1p, b0, (t - 16) * 32, lane, mb + buf * 16);
                ph[sl] ^= 1;
                sl ^= 1;
            }
        }
        return;
    }

    /* =================== CONSUMER WARPS (0..7) =================== */
    /* prologue: A(0) with zero recurrent gates; then publish fA = +1 */
    {
        if (tid < 128) dins[tid] = x[(size_t)(b0 + tid) * TT + 0];
        CBAR();
        float accZ[2][4][4];
#pragma unroll
        for (int a = 0; a < 2; a++)
#pragma unroll
            for (int b = 0; b < 4; b++)
#pragma unroll
                for (int c = 0; c < 4; c++) accZ[a][b][c] = 0.f;
        pointwise_frag(accZ, c0st, bv0, wv0, true, dins, wm, grp, tig,
                       g_h0[0], b0, ug, false, hw, slot);
        __threadfence();
        CBAR();
        if (tid == 0) gfA[mbk][nc] = myA0 + 1u;
    }

    int cs = 0, cph = 0;
#pragma unroll 1
    for (int s = 0; s < TT + HOR; s++) {
        /* weight switches (smem is CTA-private; CBARs fence all consumer reads) */
        if (s == TT - 1) {
            CBAR();
            load_w1(smem, dWhh0, 0, n0, tid, NCON);
            load_gv(bv0, db0, ug[0], ug[1]);
            load_gv(wv0, dWih0, ug[0], ug[1]);
            CBAR();
        }
        if (s == TT) {
            CBAR();
            load_w1(smem, dWih1, WS_BYTES, n0, tid, NCON);
            load_w1(smem, dWhh1, 2 * WS_BYTES, n0, tid, NCON);
            load_gv(bv1, db1, ug[0], ug[1]);
            CBAR();
        }

        float accA[2][4][4], accB[2][4][4];
#pragma unroll
        for (int a = 0; a < 2; a++)
#pragma unroll
            for (int b = 0; b < 4; b++)
#pragma unroll
                for (int c = 0; c < 4; c++) { accA[a][b][c] = 0.f; accB[a][b][c] = 0.f; }

#pragma unroll 1
        for (int ch = 0; ch < 16; ch++) {             // h0(s): dual MMA
            mb_wait(mb + cs * 16, (uint32_t)cph);
            chunk_dual32(accA, accB, ring + cs * STAGE_BYTES, ws0, ws1, ch, wm, wn, lane);
            if (lane == 0) mb_arrive(mb + cs * 16 + 8);
            if (++cs == NBUF) { cs = 0; cph ^= 1; }
        }
#pragma unroll 1
        for (int ch = 0; ch < 16; ch++) {             // h1(s-1): single MMA
            mb_wait(mb + cs * 16, (uint32_t)cph);
            chunk_one32(accB, ring + cs * STAGE_BYTES, ws2, ch, wm, wn, lane);
            if (lane == 0) mb_arrive(mb + cs * 16 + 8);
            if (++cs == NBUF) { cs = 0; cph ^= 1; }
        }

        const bool dec = (s >= TT);
        /* pointwise B(s): h1(s), c1, head partials in decoder */
        pointwise_frag(accB, c1st, bv1, wv0, false, dins, wm, grp, tig,
                       g_h1[s & 1], b0, ug, dec, hw, slot);

        if (dec) {
            group_bar_c(tid, mbk);                    // all-to-all: g_part2 + h1
            if (tid == 0) gfB[mbk][nc] = myB0 + (unsigned)(s + 1);
            if (tid < 128) {
                float v = hb;
                const float4* gp = (const float4*)(g_part2 + (size_t)(b0 + tid) * 64);
#pragma unroll
                for (int q = 0; q < 16; q++) {
                    float4 t = __ldcg(&gp[q]);
                    v += t.x + t.y + t.z + t.w;
                }
                if (nc == 0) out[(size_t)(b0 + tid) * HOR + (s - TT)] = v;
                dins[tid] = v;
            }
            CBAR();
        } else {
            if (tid < 128) {
                int nx = (s + 1 < TT) ? (s + 1) : (TT - 1);
                dins[tid] = x[(size_t)(b0 + tid) * TT + nx];
            }
            __threadfence();                          // h1 stores -> flag order
            CBAR();
            if (tid == 0) gfB[mbk][nc] = myB0 + (unsigned)(s + 1);
        }

        if (s + 1 < TT + HOR) {
            /* pointwise A(s+1): h0(s+1), c0 */
            pointwise_frag(accA, c0st, bv0, wv0, true, dins, wm, grp, tig,
                           g_h0[(s + 1) & 1], b0, ug, false, hw, slot);
            __threadfence();
            CBAR();
            if (tid == 0) gfA[mbk][nc] = myA0 + (unsigned)(s + 2);
        }
    }
}

extern "C" void kernel_launch(void* const* d_in, const int* in_sizes, int n_in,
                              void* d_out, int out_size) {
    cudaFuncSetAttribute(lstm_persistent_kernel,
                         cudaFuncAttributeMaxDynamicSharedMemorySize, SMEM_BYTES);
    lstm_persistent_kernel<<<NCTA, NTHR, SMEM_BYTES>>>(
        (const float*)d_in[0],
        (const float*)d_in[1], (const float*)d_in[2], (const float*)d_in[3],
        (const float*)d_in[4], (const float*)d_in[5], (const float*)d_in[6],
        (const float*)d_in[7], (const float*)d_in[8], (const float*)d_in[9],
        (const float*)d_in[10], (const float*)d_in[11], (const float*)d_in[12],
        (const float*)d_in[13], (const float*)d_in[14],
        (float*)d_out);
}

// round 14
// speedup vs baseline: 1.6516x; 1.6516x over previous
#include <cuda_runtime.h>
#include <cuda_fp16.h>
#include <stdint.h>

#define BB   512
#define TT   256
#define HHID 512
#define HOR  64
#define NCTA 128
#define NGRP 32                         /* CTAs per independent batch group */
#define NTHR 320                        /* 8 consumer warps + 2 producer warps */
#define NCON 256
#define WS_BYTES    65536               /* one matrix slice: 64 rows x 512 halves */
#define RING_OFF    (3 * WS_BYTES)      /* 196608 */
#define STAGE_BYTES 8192                /* K=32 chunk: 128 rows folded to 64x128B */
#define NBUF 4
#define DINS_OFF    (RING_OFF + NBUF * STAGE_BYTES)   /* 229376 */
#define MBAR_OFF    (DINS_OFF + 512)                  /* 229888 */
#define SMEM_BYTES  (MBAR_OFF + 128)                  /* 230016 */

__device__ __align__(128) __half g_h0[2][BB * HHID];
__device__ __align__(128) __half g_h1[2][BB * HHID];
__device__ float  g_part2[BB * 64];     /* [row][slot], slot = nc*2 + (warp&1) */
__device__ unsigned g_count0 = 0u;              /* init barrier (global) */
__device__ volatile unsigned g_gen0v = 0u;
__device__ unsigned g_count4[4] = {0u, 0u, 0u, 0u};   /* per-group barriers */
__device__ volatile unsigned g_gen4[4] = {0u, 0u, 0u, 0u};

/* ---------- barriers ---------- */
__device__ __forceinline__ void grid_bar_full() {      // ALL CTAs, init only
    __syncthreads();
    __threadfence();
    if (threadIdx.x == 0) {
        unsigned g = g_gen0v;
        if (atomicAdd(&g_count0, 1u) == NCTA - 1) {
            g_count0 = 0u; __threadfence(); g_gen0v = g + 1u;
        } else { while (g_gen0v == g) { } }
        __threadfence();
    }
    __syncthreads();
}
#define CBAR() asm volatile("bar.sync 1, %0;" :: "n"(NCON) : "memory")
__device__ __forceinline__ void group_bar_c(int tid, int grp_id) {  // consumers, own group
    CBAR();
    __threadfence();
    if (tid == 0) {
        unsigned g = g_gen4[grp_id];
        if (atomicAdd(&g_count4[grp_id], 1u) == NGRP - 1) {
            g_count4[grp_id] = 0u; __threadfence(); g_gen4[grp_id] = g + 1u;
        } else { while (g_gen4[grp_id] == g) { } }
        __threadfence();
    }
    CBAR();
}

/* ---------- mbarrier ---------- */
__device__ __forceinline__ void mb_init(uint32_t a, uint32_t cnt) {
    asm volatile("mbarrier.init.shared.b64 [%0], %1;" :: "r"(a), "r"(cnt) : "memory");
}
__device__ __forceinline__ void mb_arrive(uint32_t a) {
    asm volatile("mbarrier.arrive.shared.b64 _, [%0];" :: "r"(a) : "memory");
}
__device__ __forceinline__ void mb_wait(uint32_t a, uint32_t par) {
    asm volatile(
        "{\n\t.reg .pred P;\n\t"
        "LW_%=:\n\t"
        "mbarrier.try_wait.parity.acquire.cta.shared::cta.b64 P, [%0], %1, 0x989680;\n\t"
        "@P bra.uni LD_%=;\n\t"
        "bra.uni LW_%=;\n\t"
        "LD_%=:\n\t}"
        :: "r"(a), "r"(par) : "memory");
}

/* ---------- async copy / mma ---------- */
__device__ __forceinline__ void cpa16(uint32_t dst, const void* src) {
    asm volatile("cp.async.cg.shared.global [%0], [%1], 16;\n" :: "r"(dst), "l"(src));
}
__device__ __forceinline__ void ldsm4(uint32_t* r, uint32_t a) {
    asm volatile("ldmatrix.sync.aligned.m8n8.x4.shared.b16 {%0,%1,%2,%3}, [%4];\n"
                 : "=r"(r[0]), "=r"(r[1]), "=r"(r[2]), "=r"(r[3]) : "r"(a));
}
#define MMA(d, A, B0, B1)                                                      \
    asm volatile("mma.sync.aligned.m16n8k16.row.col.f32.f16.f16.f32 "          \
                 "{%0,%1,%2,%3},{%4,%5,%6,%7},{%8,%9},{%0,%1,%2,%3};"          \
                 : "+f"(d[0]), "+f"(d[1]), "+f"(d[2]), "+f"(d[3])              \
                 : "r"(A[0]), "r"(A[1]), "r"(A[2]), "r"(A[3]), "r"(B0), "r"(B1))

/* producer: stage one K=32 chunk (128 rows x 32 halves) with 1 warp */
__device__ __forceinline__ void p_stage(uint32_t ring, int buf, const __half* hsrc,
                                        int b0, int kc, int lane, uint32_t fullbar) {
    uint32_t base = ring + buf * STAGE_BYTES;
#pragma unroll
    for (int u = 0; u < 16; u++) {
        int i = lane + u * 32;              // 0..511 16B blocks
        int br = i >> 2, cb4 = i & 3;
        int phys = (cb4 + ((br >> 6) << 2)) ^ (br & 7);
        cpa16(base + (br & 63) * 128 + (phys << 4),
              hsrc + (size_t)(b0 + br) * HHID + kc + cb4 * 8);
    }
    asm volatile("cp.async.mbarrier.arrive.noinc.shared.b64 [%0];" :: "r"(fullbar) : "memory");
}

/* dual chunk, 32x32 tile, W-prefetch BEFORE the ring wait:
   accA += A x W0^T, accB += A x W1^T (shared A fragments) */
__device__ __forceinline__ void chunk_dual32_pre(float aA[2][4][4], float aB[2][4][4],
                                                 uint32_t Ast, uint32_t W0, uint32_t W1,
                                                 int chk, int wm, int wn, int lane,
                                                 uint32_t fullbar, uint32_t par) {
    const int a_row = lane & 15, akc = lane >> 4;
    const int b_row = (lane & 7) + ((lane >> 4) << 3), bkc = (lane >> 3) & 1;
    const int R0 = wn + b_row, R1 = R0 + 16;
    const int R07 = R0 & 7, R17 = R1 & 7;
    const uint32_t W0r0 = W0 + R0 * 1024, W0r1 = W0 + R1 * 1024;
    const uint32_t W1r0 = W1 + R0 * 1024, W1r1 = W1 + R1 * 1024;
    const int lr0 = wm + a_row, lr1 = lr0 + 16;
    const uint32_t Ar0 = Ast + (lr0 & 63) * 128, Ar1 = Ast + (lr1 & 63) * 128;
    const int hb0 = (lr0 >> 6) << 2, hb1 = (lr1 >> 6) << 2;
    const int l07 = lr0 & 7, l17 = lr1 & 7;
    const int cb0 = chk * 4 + bkc, cb1 = cb0 + 2;

    /* ---- W fragments: independent of ring buffer, load before wait ---- */
    uint32_t C0a[4], C0b[4], B0a[4], B0b[4], C1a[4], C1b[4], B1a[4], B1b[4];
    ldsm4(C0a, W0r0 + ((cb0 ^ R07) << 4));
    ldsm4(C0b, W0r1 + ((cb0 ^ R17) << 4));
    ldsm4(B0a, W1r0 + ((cb0 ^ R07) << 4));
    ldsm4(B0b, W1r1 + ((cb0 ^ R17) << 4));
    ldsm4(C1a, W0r0 + ((cb1 ^ R07) << 4));
    ldsm4(C1b, W0r1 + ((cb1 ^ R17) << 4));
    ldsm4(B1a, W1r0 + ((cb1 ^ R07) << 4));
    ldsm4(B1b, W1r1 + ((cb1 ^ R17) << 4));

    mb_wait(fullbar, par);

    uint32_t A0[4], A1[4];
    /* kk = 0 */
    ldsm4(A0, Ar0 + ((((akc + hb0) ^ l07)) << 4));
    ldsm4(A1, Ar1 + ((((akc + hb1) ^ l17)) << 4));
    MMA(aB[0][0], A0, B0a[0], B0a[1]);
    MMA(aB[0][1], A0, B0a[2], B0a[3]);
    MMA(aB[0][2], A0, B0b[0], B0b[1]);
    MMA(aB[0][3], A0, B0b[2], B0b[3]);
    MMA(aB[1][0], A1, B0a[0], B0a[1]);
    MMA(aB[1][1], A1, B0a[2], B0a[3]);
    MMA(aB[1][2], A1, B0b[0], B0b[1]);
    MMA(aB[1][3], A1, B0b[2], B0b[3]);
    MMA(aA[0][0], A0, C0a[0], C0a[1]);
    MMA(aA[0][1], A0, C0a[2], C0a[3]);
    MMA(aA[0][2], A0, C0b[0], C0b[1]);
    MMA(aA[0][3], A0, C0b[2], C0b[3]);
    MMA(aA[1][0], A1, C0a[0], C0a[1]);
    MMA(aA[1][1], A1, C0a[2], C0a[3]);
    MMA(aA[1][2], A1, C0b[0], C0b[1]);
    MMA(aA[1][3], A1, C0b[2], C0b[3]);
    /* kk = 16 (k8 = 2) */
    ldsm4(A0, Ar0 + ((((2 + akc + hb0) ^ l07)) << 4));
    ldsm4(A1, Ar1 + ((((2 + akc + hb1) ^ l17)) << 4));
    MMA(aB[0][0], A0, B1a[0], B1a[1]);
    MMA(aB[0][1], A0, B1a[2], B1a[3]);
    MMA(aB[0][2], A0, B1b[0], B1b[1]);
    MMA(aB[0][3], A0, B1b[2], B1b[3]);
    MMA(aB[1][0], A1, B1a[0], B1a[1]);
    MMA(aB[1][1], A1, B1a[2], B1a[3]);
    MMA(aB[1][2], A1, B1b[0], B1b[1]);
    MMA(aB[1][3], A1, B1b[2], B1b[3]);
    MMA(aA[0][0], A0, C1a[0], C1a[1]);
    MMA(aA[0][1], A0, C1a[2], C1a[3]);
    MMA(aA[0][2], A0, C1b[0], C1b[1]);
    MMA(aA[0][3], A0, C1b[2], C1b[3]);
    MMA(aA[1][0], A1, C1a[0], C1a[1]);
    MMA(aA[1][1], A1, C1a[2], C1a[3]);
    MMA(aA[1][2], A1, C1b[0], C1b[1]);
    MMA(aA[1][3], A1, C1b[2], C1b[3]);
}

/* single chunk, 32x32 tile, W-prefetch before wait: accB += A x W^T */
__device__ __forceinline__ void chunk_one32_pre(float aB[2][4][4],
                                                uint32_t Ast, uint32_t W1,
                                                int chk, int wm, int wn, int lane,
                                                uint32_t fullbar, uint32_t par) {
    const int a_row = lane & 15, akc = lane >> 4;
    const int b_row = (lane & 7) + ((lane >> 4) << 3), bkc = (lane >> 3) & 1;
    const int R0 = wn + b_row, R1 = R0 + 16;
    const int R07 = R0 & 7, R17 = R1 & 7;
    const uint32_t W1r0 = W1 + R0 * 1024, W1r1 = W1 + R1 * 1024;
    const int lr0 = wm + a_row, lr1 = lr0 + 16;
    const uint32_t Ar0 = Ast + (lr0 & 63) * 128, Ar1 = Ast + (lr1 & 63) * 128;
    const int hb0 = (lr0 >> 6) << 2, hb1 = (lr1 >> 6) << 2;
    const int l07 = lr0 & 7, l17 = lr1 & 7;
    const int cb0 = chk * 4 + bkc, cb1 = cb0 + 2;

    uint32_t B0a[4], B0b[4], B1a[4], B1b[4];
    ldsm4(B0a, W1r0 + ((cb0 ^ R07) << 4));
    ldsm4(B0b, W1r1 + ((cb0 ^ R17) << 4));
    ldsm4(B1a, W1r0 + ((cb1 ^ R07) << 4));
    ldsm4(B1b, W1r1 + ((cb1 ^ R17) << 4));

    mb_wait(fullbar, par);

    uint32_t A0[4], A1[4];
    ldsm4(A0, Ar0 + ((((akc + hb0) ^ l07)) << 4));
    ldsm4(A1, Ar1 + ((((akc + hb1) ^ l17)) << 4));
    MMA(aB[0][0], A0, B0a[0], B0a[1]);
    MMA(aB[0][1], A0, B0a[2], B0a[3]);
    MMA(aB[0][2], A0, B0b[0], B0b[1]);
    MMA(aB[0][3], A0, B0b[2], B0b[3]);
    MMA(aB[1][0], A1, B0a[0], B0a[1]);
    MMA(aB[1][1], A1, B0a[2], B0a[3]);
    MMA(aB[1][2], A1, B0b[0], B0b[1]);
    MMA(aB[1][3], A1, B0b[2], B0b[3]);
    ldsm4(A0, Ar0 + ((((2 + akc + hb0) ^ l07)) << 4));
    ldsm4(A1, Ar1 + ((((2 + akc + hb1) ^ l17)) << 4));
    MMA(aB[0][0], A0, B1a[0], B1a[1]);
    MMA(aB[0][1], A0, B1a[2], B1a[3]);
    MMA(aB[0][2], A0, B1b[0], B1b[1]);
    MMA(aB[0][3], A0, B1b[2], B1b[3]);
    MMA(aB[1][0], A1, B1a[0], B1a[1]);
    MMA(aB[1][1], A1, B1a[2], B1a[3]);
    MMA(aB[1][2], A1, B1b[0], B1b[1]);
    MMA(aB[1][3], A1, B1b[2], B1b[3]);
}

/* convert ONE weight matrix 64-row slice fp32 -> fp16 into swizzled smem slot */
__device__ void load_w1(char* smem, const float* W, int moff, int n0, int tid, int nthr) {
    for (int i = tid; i < 64 * 512; i += nthr) {
        int r = i >> 9, k = i & 511;
        int pr = n0 + r, j = pr >> 2, g = pr & 3;
        float v = W[(size_t)(g * 512 + j) * HHID + k];
        int ck = k >> 3;
        int off = moff + r * 1024 + (((ck ^ (r & 7)) << 4)) + (k & 7) * 2;
        *(__half*)(smem + off) = __float2half(v);
    }
}

__device__ __forceinline__ void load_gv(float d[2][4], const float* b, int u0, int u1) {
    d[0][0] = b[u0]; d[0][1] = b[512 + u0]; d[0][2] = b[1024 + u0]; d[0][3] = b[1536 + u0];
    d[1][0] = b[u1]; d[1][1] = b[512 + u1]; d[1][2] = b[1024 + u1]; d[1][3] = b[1536 + u1];
}

/* HW tanh (sm_75+): max abs err ~6e-4, within budget (verified R11/R12) */
__device__ __forceinline__ float tanhap(float z) {
    float r;
    asm("tanh.approx.f32 %0, %1;" : "=f"(r) : "f"(z));
    return r;
}
__device__ __forceinline__ float sigf(float z) { return 0.5f * tanhap(0.5f * z) + 0.5f; }

/* balanced in-register LSTM pointwise for 32x32 tiles (verified layout) */
__device__ __forceinline__ void pointwise_frag(
    const float acc[2][4][4], float* cst /*[8]*/,
    const float bv[2][4], const float wv[2][4], bool use_w,
    const float* dins, int wm, int grp, int tig,
    __half* hout, int b0, const int* ug,
    bool do_head, const float* hw, int slot) {
    const unsigned FULL = 0xFFFFFFFFu;
    float pv[4] = {0.f, 0.f, 0.f, 0.f};
#pragma unroll
    for (int mf = 0; mf < 2; mf++) {
        int r0 = wm + mf * 16 + grp;
        float va = use_w ? dins[r0] : 0.f;
        float vb = use_w ? dins[r0 + 8] : 0.f;
#pragma unroll
        for (int nf = 0; nf < 4; nf++) {
            float e0 = __shfl_xor_sync(FULL, acc[mf][nf][0], 1);
            float e1 = __shfl_xor_sync(FULL, acc[mf][nf][1], 1);
            float e2 = __shfl_xor_sync(FULL, acc[mf][nf][2], 1);
            float e3 = __shfl_xor_sync(FULL, acc[mf][nf][3], 1);
            if (((nf ^ tig) & 1) == 0) {
                int no = nf >> 1;
                float zi0, zf0, zg0, zo0, zi1, zf1, zg1, zo1;
                if ((tig & 1) == 0) {
                    zi0 = acc[mf][nf][0]; zf0 = acc[mf][nf][1]; zg0 = e0; zo0 = e1;
                    zi1 = acc[mf][nf][2]; zf1 = acc[mf][nf][3]; zg1 = e2; zo1 = e3;
                } else {
                    zg0 = acc[mf][nf][0]; zo0 = acc[mf][nf][1]; zi0 = e0; zf0 = e1;
                    zg1 = acc[mf][nf][2]; zo1 = acc[mf][nf][3]; zi1 = e2; zf1 = e3;
                }
                zi0 += bv[no][0]; zf0 += bv[no][1]; zg0 += bv[no][2]; zo0 += bv[no][3];
                zi1 += bv[no][0]; zf1 += bv[no][1]; zg1 += bv[no][2]; zo1 += bv[no][3];
                if (use_w) {
                    zi0 += va * wv[no][0]; zf0 += va * wv[no][1];
                    zg0 += va * wv[no][2]; zo0 += va * wv[no][3];
                    zi1 += vb * wv[no][0]; zf1 += vb * wv[no][1];
                    zg1 += vb * wv[no][2]; zo1 += vb * wv[no][3];
                }
                int ci = mf * 4 + no * 2;
                float cA = sigf(zf0) * cst[ci]     + sigf(zi0) * tanhap(zg0);
                float cB = sigf(zf1) * cst[ci + 1] + sigf(zi1) * tanhap(zg1);
                cst[ci] = cA; cst[ci + 1] = cB;
                float hA = sigf(zo0) * tanhap(cA);
                float hB = sigf(zo1) * tanhap(cB);
                hout[(size_t)(b0 + r0) * HHID + ug[no]]     = __float2half(hA);
                hout[(size_t)(b0 + r0 + 8) * HHID + ug[no]] = __float2half(hB);
                if (do_head) {
                    pv[mf * 2]     += hA * hw[no];
                    pv[mf * 2 + 1] += hB * hw[no];
                }
            }
        }
    }
    if (do_head) {
#pragma unroll
        for (int q = 0; q < 4; q++) {
            float sv = pv[q] + __shfl_xor_sync(FULL, pv[q], 1);
            sv += __shfl_xor_sync(FULL, sv, 2);
            if (tig == 0) {
                int row = wm + (q >> 1) * 16 + grp + (q & 1) * 8;
                g_part2[(size_t)(b0 + row) * 64 + slot] = sv;
            }
        }
    }
}

__global__ void __launch_bounds__(NTHR, 1)
lstm_persistent_kernel(const float* __restrict__ x,
                       const float* __restrict__ eWih0, const float* __restrict__ eWhh0,
                       const float* __restrict__ eb0,
                       const float* __restrict__ eWih1, const float* __restrict__ eWhh1,
                       const float* __restrict__ eb1,
                       const float* __restrict__ dWih0, const float* __restrict__ dWhh0,
                       const float* __restrict__ db0,
                       const float* __restrict__ dWih1, const float* __restrict__ dWhh1,
                       const float* __restrict__ db1,
                       const float* __restrict__ headW, const float* __restrict__ headb,
                       float* __restrict__ out) {
    extern __shared__ __align__(1024) char smem[];
    uint32_t sb;
    asm("{ .reg .u64 t; cvta.to.shared.u64 t, %1; cvt.u32.u64 %0, t; }"
        : "=r"(sb) : "l"(smem));
    const uint32_t ws0 = sb, ws1 = sb + WS_BYTES, ws2 = sb + 2 * WS_BYTES;
    const uint32_t ring = sb + RING_OFF;
    float* dins = (float*)(smem + DINS_OFF);
    const uint32_t mb = sb + MBAR_OFF;      // full[s]=mb+16s, empty[s]=mb+16s+8

    const int tid  = threadIdx.x;
    const int lane = tid & 31, warp = tid >> 5;
    const int cta  = blockIdx.x;
    const int mbk  = cta >> 5, nc = cta & 31;
    const int b0   = mbk * 128, n0 = nc * 64;
    const int wm   = ((warp & 7) >> 1) * 32, wn = (warp & 1) * 32;
    const int grp  = lane >> 2, tig = lane & 3;
    const int slot = nc * 2 + (warp & 1);

    int ug[2];
    ug[0] = nc * 16 + (wn >> 2) + ((tig & 1) ? 2 : 0) + (tig >> 1);
    ug[1] = ug[0] + 4;

    /* group-gen snapshot BEFORE global init barrier -> launch-idempotent gating */
    const unsigned gen0 = g_gen4[mbk];

    /* ---- init ---- */
    if (tid == 0) {
#pragma unroll
        for (int s = 0; s < NBUF; s++) {
            mb_init(mb + s * 16, 32);       // full: 32 producer-lane arrivals
            mb_init(mb + s * 16 + 8, 8);    // empty: 8 consumer-warp arrivals
        }
    }
    load_w1(smem, eWhh0, 0, n0, tid, NTHR);
    load_w1(smem, eWih1, WS_BYTES, n0, tid, NTHR);
    load_w1(smem, eWhh1, 2 * WS_BYTES, n0, tid, NTHR);
    {
        int gtid = cta * NTHR + tid;
        for (int i = gtid; i < BB * HHID; i += NCTA * NTHR)
            g_h1[1][i] = __float2half(0.f);   // h1(-1) = 0
    }
    float bv0[2][4], wv0[2][4], bv1[2][4], hw[2];
    load_gv(bv0, eb0, ug[0], ug[1]);
    load_gv(wv0, eWih0, ug[0], ug[1]);
    load_gv(bv1, eb1, ug[0], ug[1]);
    hw[0] = headW[ug[0]]; hw[1] = headW[ug[1]];
    const float hb = headb[0];
    float c0st[8], c1st[8];
#pragma unroll
    for (int i = 0; i < 8; i++) { c0st[i] = 0.f; c1st[i] = 0.f; }

    /* prologue: A(0) with zero recurrent gates (consumers only) */
    if (warp < 8) {
        if (tid < 128) dins[tid] = x[(size_t)(b0 + tid) * TT + 0];
        CBAR();
        float accZ[2][4][4];
#pragma unroll
        for (int a = 0; a < 2; a++)
#pragma unroll
            for (int b = 0; b < 4; b++)
#pragma unroll
                for (int c = 0; c < 4; c++) accZ[a][b][c] = 0.f;
        pointwise_frag(accZ, c0st, bv0, wv0, true, dins, wm, grp, tig,
                       g_h0[0], b0, ug, false, hw, slot);
    }
    grid_bar_full();   // global: publishes h0(0), zeros, mbarrier inits

    if (warp >= 8) {
        /* =================== PRODUCER WARPS (8, 9) =================== */
        const int pidx = warp - 8;          // handles chunks with (t & 1) == pidx
        int ph[2] = {1, 1};                 // per-slot parity (slots pidx, pidx+2)
        int sl = 0;                         // which of my two slots next
#pragma unroll 1
        for (int s = 0; s < TT + HOR; s++) {
            unsigned need = (unsigned)((s <= TT) ? s : (TT + 2 * (s - TT)));
            while ((unsigned)(g_gen4[mbk] - gen0) < need) { }
            __threadfence();
            const __half* h0s = g_h0[s & 1];
            const __half* h1p = g_h1[(s & 1) ^ 1];
#pragma unroll 1
            for (int ch = pidx; ch < 32; ch += 2) {
                int buf = (sl == 0) ? pidx : (pidx + 2);
                mb_wait(mb + buf * 16 + 8, (uint32_t)ph[sl]);
                if (ch < 16)
                    p_stage(ring, buf, h0s, b0, ch * 32, lane, mb + buf * 16);
                else
                    p_stage(ring, buf, h1p, b0, (ch - 16) * 32, lane, mb + buf * 16);
                ph[sl] ^= 1;
                sl ^= 1;
            }
        }
        return;
    }

    /* =================== CONSUMER WARPS (0..7) =================== */
    int cs = 0, cph = 0;
#pragma unroll 1
    for (int s = 0; s < TT + HOR; s++) {
        /* weight switches (smem is CTA-private; CBARs fence all consumer reads) */
        if (s == TT - 1) {
            CBAR();
            load_w1(smem, dWhh0, 0, n0, tid, NCON);
            load_gv(bv0, db0, ug[0], ug[1]);
            load_gv(wv0, dWih0, ug[0], ug[1]);
            CBAR();
        }
        if (s == TT) {
            CBAR();
            load_w1(smem, dWih1, WS_BYTES, n0, tid, NCON);
            load_w1(smem, dWhh1, 2 * WS_BYTES, n0, tid, NCON);
            load_gv(bv1, db1, ug[0], ug[1]);
            CBAR();
        }

        float accA[2][4][4], accB[2][4][4];
#pragma unroll
        for (int a = 0; a < 2; a++)
#pragma unroll
            for (int b = 0; b < 4; b++)
#pragma unroll
                for (int c = 0; c < 4; c++) { accA[a][b][c] = 0.f; accB[a][b][c] = 0.f; }

#pragma unroll 1
        for (int ch = 0; ch < 16; ch++) {             // h0(s): dual MMA (W pre-wait)
            chunk_dual32_pre(accA, accB, ring + cs * STAGE_BYTES, ws0, ws1,
                             ch, wm, wn, lane, mb + cs * 16, (uint32_t)cph);
            if (lane == 0) mb_arrive(mb + cs * 16 + 8);
            if (++cs == NBUF) { cs = 0; cph ^= 1; }
        }
#pragma unroll 1
        for (int ch = 0; ch < 16; ch++) {             // h1(s-1): single MMA (W pre-wait)
            chunk_one32_pre(accB, ring + cs * STAGE_BYTES, ws2,
                            ch, wm, wn, lane, mb + cs * 16, (uint32_t)cph);
            if (lane == 0) mb_arrive(mb + cs * 16 + 8);
            if (++cs == NBUF) { cs = 0; cph ^= 1; }
        }

        const bool dec = (s >= TT);
        /* pointwise B(s): h1(s), c1, head partials in decoder */
        pointwise_frag(accB, c1st, bv1, wv0, false, dins, wm, grp, tig,
                       g_h1[s & 1], b0, ug, dec, hw, slot);

        if (dec) {
            group_bar_c(tid, mbk);                    // mid bar: publish g_part2
            if (tid < 128) {
                float v = hb;
                const float4* gp = (const float4*)(g_part2 + (size_t)(b0 + tid) * 64);
#pragma unroll
                for (int q = 0; q < 16; q++) {
                    float4 t = __ldcg(&gp[q]);
                    v += t.x + t.y + t.z + t.w;
                }
                if (nc == 0) out[(size_t)(b0 + tid) * HOR + (s - TT)] = v;
                dins[tid] = v;
            }
            CBAR();
        } else {
            int nx = (s + 1 < TT) ? (s + 1) : (TT - 1);
            if (tid < 128) dins[tid] = x[(size_t)(b0 + tid) * TT + nx];
            CBAR();
        }

        if (s + 1 < TT + HOR) {
            /* pointwise A(s+1): h0(s+1), c0 */
            pointwise_frag(accA, c0st, bv0, wv0, true, dins, wm, grp, tig,
                           g_h0[(s + 1) & 1], b0, ug, false, hw, slot);
            group_bar_c(tid, mbk);                    // end bar: publish h0(s+1), h1(s)
        }
    }
}

extern "C" void kernel_launch(void* const* d_in, const int* in_sizes, int n_in,
                              void* d_out, int out_size) {
    cudaFuncSetAttribute(lstm_persistent_kernel,
                         cudaFuncAttributeMaxDynamicSharedMemorySize, SMEM_BYTES);
    lstm_persistent_kernel<<<NCTA, NTHR, SMEM_BYTES>>>(
        (const float*)d_in[0],
        (const float*)d_in[1], (const float*)d_in[2], (const float*)d_in[3],
        (const float*)d_in[4], (const float*)d_in[5], (const float*)d_in[6],
        (const float*)d_in[7], (const float*)d_in[8], (const float*)d_in[9],
        (const float*)d_in[10], (const float*)d_in[11], (const float*)d_in[12],
        (const float*)d_in[13], (const float*)d_in[14],
        (float*)d_out);
}

// round 15
// speedup vs baseline: 1.8280x; 1.1068x over previous
#include <cuda_runtime.h>
#include <cuda_fp16.h>
#include <stdint.h>

#define BB   512
#define TT   256
#define HHID 512
#define HOR  64
#define NCTA 128
#define NGRP 32                         /* CTAs per independent batch group */
#define NTHR 320                        /* 8 consumer warps + 2 producer warps */
#define NCON 256
#define WS_BYTES    65536               /* one matrix slice: 64 rows x 512 halves */
#define RING_OFF    (3 * WS_BYTES)      /* 196608 */
#define STAGE_BYTES 8192                /* K=32 chunk: 128 rows folded to 64x128B */
#define NBUF 4
#define DINS_OFF    (RING_OFF + NBUF * STAGE_BYTES)   /* 229376 */
#define MBAR_OFF    (DINS_OFF + 512)                  /* 229888 */
#define SMEM_BYTES  (MBAR_OFF + 128)                  /* 230016 */

__device__ __align__(128) __half g_h0[2][BB * HHID];
__device__ __align__(128) __half g_h1[2][BB * HHID];
__device__ float  g_part2[BB * 64];     /* [row][slot], slot = nc*2 + (warp&1) */
__device__ unsigned g_count0 = 0u;              /* init barrier (global) */
__device__ volatile unsigned g_gen0v = 0u;
__device__ unsigned g_count4[4] = {0u, 0u, 0u, 0u};   /* per-group barriers */
__device__ volatile unsigned g_gen4[4] = {0u, 0u, 0u, 0u};

/* ---------- barriers ---------- */
__device__ __forceinline__ void grid_bar_full() {      // ALL CTAs, init only
    __syncthreads();
    __threadfence();
    if (threadIdx.x == 0) {
        unsigned g = g_gen0v;
        if (atomicAdd(&g_count0, 1u) == NCTA - 1) {
            g_count0 = 0u; __threadfence(); g_gen0v = g + 1u;
        } else { while (g_gen0v == g) { } }
        __threadfence();
    }
    __syncthreads();
}
#define CBAR() asm volatile("bar.sync 1, %0;" :: "n"(NCON) : "memory")
__device__ __forceinline__ void group_bar_c(int tid, int grp_id) {  // consumers, own group
    CBAR();
    __threadfence();
    if (tid == 0) {
        unsigned g = g_gen4[grp_id];
        if (atomicAdd(&g_count4[grp_id], 1u) == NGRP - 1) {
            g_count4[grp_id] = 0u; __threadfence(); g_gen4[grp_id] = g + 1u;
        } else { while (g_gen4[grp_id] == g) { } }
        __threadfence();
    }
    CBAR();
}

/* ---------- mbarrier ---------- */
__device__ __forceinline__ void mb_init(uint32_t a, uint32_t cnt) {
    asm volatile("mbarrier.init.shared.b64 [%0], %1;" :: "r"(a), "r"(cnt) : "memory");
}
__device__ __forceinline__ void mb_arrive(uint32_t a) {
    asm volatile("mbarrier.arrive.shared.b64 _, [%0];" :: "r"(a) : "memory");
}
__device__ __forceinline__ void mb_wait(uint32_t a, uint32_t par) {
    asm volatile(
        "{\n\t.reg .pred P;\n\t"
        "LW_%=:\n\t"
        "mbarrier.try_wait.parity.acquire.cta.shared::cta.b64 P, [%0], %1, 0x989680;\n\t"
        "@P bra.uni LD_%=;\n\t"
        "bra.uni LW_%=;\n\t"
        "LD_%=:\n\t}"
        :: "r"(a), "r"(par) : "memory");
}

/* ---------- async copy / mma ---------- */
__device__ __forceinline__ void cpa16(uint32_t dst, const void* src) {
    asm volatile("cp.async.cg.shared.global [%0], [%1], 16;\n" :: "r"(dst), "l"(src));
}
__device__ __forceinline__ void ldsm4(uint32_t* r, uint32_t a) {
    asm volatile("ldmatrix.sync.aligned.m8n8.x4.shared.b16 {%0,%1,%2,%3}, [%4];\n"
                 : "=r"(r[0]), "=r"(r[1]), "=r"(r[2]), "=r"(r[3]) : "r"(a));
}
#define MMA(d, A, B0, B1)                                                      \
    asm volatile("mma.sync.aligned.m16n8k16.row.col.f32.f16.f16.f32 "          \
                 "{%0,%1,%2,%3},{%4,%5,%6,%7},{%8,%9},{%0,%1,%2,%3};"          \
                 : "+f"(d[0]), "+f"(d[1]), "+f"(d[2]), "+f"(d[3])              \
                 : "r"(A[0]), "r"(A[1]), "r"(A[2]), "r"(A[3]), "r"(B0), "r"(B1))

/* producer: stage one K=32 chunk (128 rows x 32 halves), NO arrive */
__device__ __forceinline__ void p_stage_na(uint32_t ring, int buf, const __half* hsrc,
                                           int b0, int kc, int lane) {
    uint32_t base = ring + buf * STAGE_BYTES;
#pragma unroll
    for (int u = 0; u < 16; u++) {
        int i = lane + u * 32;              // 0..511 16B blocks
        int br = i >> 2, cb4 = i & 3;
        int phys = (cb4 + ((br >> 6) << 2)) ^ (br & 7);
        cpa16(base + (br & 63) * 128 + (phys << 4),
              hsrc + (size_t)(b0 + br) * HHID + kc + cb4 * 8);
    }
}
#define CPA_ARRIVE(bar) \
    asm volatile("cp.async.mbarrier.arrive.noinc.shared.b64 [%0];" :: "r"(bar) : "memory")

/* dual chunk, 32x32 tile: accA += A x W0^T, accB += A x W1^T (shared A frags) */
__device__ __forceinline__ void chunk_dual32(float aA[2][4][4], float aB[2][4][4],
                                             uint32_t Ast, uint32_t W0, uint32_t W1,
                                             int chk, int wm, int wn, int lane) {
    const int a_row = lane & 15, akc = lane >> 4;
    const int b_row = (lane & 7) + ((lane >> 4) << 3), bkc = (lane >> 3) & 1;
    const int R0 = wn + b_row, R1 = R0 + 16;
    const int R07 = R0 & 7, R17 = R1 & 7;
    const uint32_t W0r0 = W0 + R0 * 1024, W0r1 = W0 + R1 * 1024;
    const uint32_t W1r0 = W1 + R0 * 1024, W1r1 = W1 + R1 * 1024;
    const int lr0 = wm + a_row, lr1 = lr0 + 16;
    const uint32_t Ar0 = Ast + (lr0 & 63) * 128, Ar1 = Ast + (lr1 & 63) * 128;
    const int hb0 = (lr0 >> 6) << 2, hb1 = (lr1 >> 6) << 2;
    const int l07 = lr0 & 7, l17 = lr1 & 7;
#pragma unroll
    for (int kk = 0; kk < 32; kk += 16) {
        int k8 = kk >> 3;
        int cb = chk * 4 + k8 + bkc;
        uint32_t Ca[4], Cb[4], Ba[4], Bb[4], A0[4], A1[4];
        ldsm4(Ca, W0r0 + ((cb ^ R07) << 4));
        ldsm4(Cb, W0r1 + ((cb ^ R17) << 4));
        ldsm4(Ba, W1r0 + ((cb ^ R07) << 4));
        ldsm4(Bb, W1r1 + ((cb ^ R17) << 4));
        ldsm4(A0, Ar0 + ((((k8 + akc + hb0) ^ l07)) << 4));
        ldsm4(A1, Ar1 + ((((k8 + akc + hb1) ^ l17)) << 4));
        MMA(aB[0][0], A0, Ba[0], Ba[1]);
        MMA(aB[0][1], A0, Ba[2], Ba[3]);
        MMA(aB[0][2], A0, Bb[0], Bb[1]);
        MMA(aB[0][3], A0, Bb[2], Bb[3]);
        MMA(aB[1][0], A1, Ba[0], Ba[1]);
        MMA(aB[1][1], A1, Ba[2], Ba[3]);
        MMA(aB[1][2], A1, Bb[0], Bb[1]);
        MMA(aB[1][3], A1, Bb[2], Bb[3]);
        MMA(aA[0][0], A0, Ca[0], Ca[1]);
        MMA(aA[0][1], A0, Ca[2], Ca[3]);
        MMA(aA[0][2], A0, Cb[0], Cb[1]);
        MMA(aA[0][3], A0, Cb[2], Cb[3]);
        MMA(aA[1][0], A1, Ca[0], Ca[1]);
        MMA(aA[1][1], A1, Ca[2], Ca[3]);
        MMA(aA[1][2], A1, Cb[0], Cb[1]);
        MMA(aA[1][3], A1, Cb[2], Cb[3]);
    }
}

/* single chunk, 32x32 tile: accB += A x W^T */
__device__ __forceinline__ void chunk_one32(float aB[2][4][4],
                                            uint32_t Ast, uint32_t W1,
                                            int chk, int wm, int wn, int lane) {
    const int a_row = lane & 15, akc = lane >> 4;
    const int b_row = (lane & 7) + ((lane >> 4) << 3), bkc = (lane >> 3) & 1;
    const int R0 = wn + b_row, R1 = R0 + 16;
    const int R07 = R0 & 7, R17 = R1 & 7;
    const uint32_t W1r0 = W1 + R0 * 1024, W1r1 = W1 + R1 * 1024;
    const int lr0 = wm + a_row, lr1 = lr0 + 16;
    const uint32_t Ar0 = Ast + (lr0 & 63) * 128, Ar1 = Ast + (lr1 & 63) * 128;
    const int hb0 = (lr0 >> 6) << 2, hb1 = (lr1 >> 6) << 2;
    const int l07 = lr0 & 7, l17 = lr1 & 7;
#pragma unroll
    for (int kk = 0; kk < 32; kk += 16) {
        int k8 = kk >> 3;
        int cb = chk * 4 + k8 + bkc;
        uint32_t Ba[4], Bb[4], A0[4], A1[4];
        ldsm4(Ba, W1r0 + ((cb ^ R07) << 4));
        ldsm4(Bb, W1r1 + ((cb ^ R17) << 4));
        ldsm4(A0, Ar0 + ((((k8 + akc + hb0) ^ l07)) << 4));
        ldsm4(A1, Ar1 + ((((k8 + akc + hb1) ^ l17)) << 4));
        MMA(aB[0][0], A0, Ba[0], Ba[1]);
        MMA(aB[0][1], A0, Ba[2], Ba[3]);
        MMA(aB[0][2], A0, Bb[0], Bb[1]);
        MMA(aB[0][3], A0, Bb[2], Bb[3]);
        MMA(aB[1][0], A1, Ba[0], Ba[1]);
        MMA(aB[1][1], A1, Ba[2], Ba[3]);
        MMA(aB[1][2], A1, Bb[0], Bb[1]);
        MMA(aB[1][3], A1, Bb[2], Bb[3]);
    }
}

/* convert ONE weight matrix 64-row slice fp32 -> fp16 into swizzled smem slot */
__device__ void load_w1(char* smem, const float* W, int moff, int n0, int tid, int nthr) {
    for (int i = tid; i < 64 * 512; i += nthr) {
        int r = i >> 9, k = i & 511;
        int pr = n0 + r, j = pr >> 2, g = pr & 3;
        float v = W[(size_t)(g * 512 + j) * HHID + k];
        int ck = k >> 3;
        int off = moff + r * 1024 + (((ck ^ (r & 7)) << 4)) + (k & 7) * 2;
        *(__half*)(smem + off) = __float2half(v);
    }
}

__device__ __forceinline__ void load_gv(float d[2][4], const float* b, int u0, int u1) {
    d[0][0] = b[u0]; d[0][1] = b[512 + u0]; d[0][2] = b[1024 + u0]; d[0][3] = b[1536 + u0];
    d[1][0] = b[u1]; d[1][1] = b[512 + u1]; d[1][2] = b[1024 + u1]; d[1][3] = b[1536 + u1];
}

/* HW tanh (sm_75+): max abs err ~6e-4, within budget (verified R11/R12) */
__device__ __forceinline__ float tanhap(float z) {
    float r;
    asm("tanh.approx.f32 %0, %1;" : "=f"(r) : "f"(z));
    return r;
}
__device__ __forceinline__ float sigf(float z) { return 0.5f * tanhap(0.5f * z) + 0.5f; }

/* balanced in-register LSTM pointwise for 32x32 tiles (verified layout) */
__device__ __forceinline__ void pointwise_frag(
    const float acc[2][4][4], float* cst /*[8]*/,
    const float bv[2][4], const float wv[2][4], bool use_w,
    const float* dins, int wm, int grp, int tig,
    __half* hout, int b0, const int* ug,
    bool do_head, const float* hw, int slot) {
    const unsigned FULL = 0xFFFFFFFFu;
    float pv[4] = {0.f, 0.f, 0.f, 0.f};
#pragma unroll
    for (int mf = 0; mf < 2; mf++) {
        int r0 = wm + mf * 16 + grp;
        float va = use_w ? dins[r0] : 0.f;
        float vb = use_w ? dins[r0 + 8] : 0.f;
#pragma unroll
        for (int nf = 0; nf < 4; nf++) {
            float e0 = __shfl_xor_sync(FULL, acc[mf][nf][0], 1);
            float e1 = __shfl_xor_sync(FULL, acc[mf][nf][1], 1);
            float e2 = __shfl_xor_sync(FULL, acc[mf][nf][2], 1);
            float e3 = __shfl_xor_sync(FULL, acc[mf][nf][3], 1);
            if (((nf ^ tig) & 1) == 0) {
                int no = nf >> 1;
                float zi0, zf0, zg0, zo0, zi1, zf1, zg1, zo1;
                if ((tig & 1) == 0) {
                    zi0 = acc[mf][nf][0]; zf0 = acc[mf][nf][1]; zg0 = e0; zo0 = e1;
                    zi1 = acc[mf][nf][2]; zf1 = acc[mf][nf][3]; zg1 = e2; zo1 = e3;
                } else {
                    zg0 = acc[mf][nf][0]; zo0 = acc[mf][nf][1]; zi0 = e0; zf0 = e1;
                    zg1 = acc[mf][nf][2]; zo1 = acc[mf][nf][3]; zi1 = e2; zf1 = e3;
                }
                zi0 += bv[no][0]; zf0 += bv[no][1]; zg0 += bv[no][2]; zo0 += bv[no][3];
                zi1 += bv[no][0]; zf1 += bv[no][1]; zg1 += bv[no][2]; zo1 += bv[no][3];
                if (use_w) {
                    zi0 += va * wv[no][0]; zf0 += va * wv[no][1];
                    zg0 += va * wv[no][2]; zo0 += va * wv[no][3];
                    zi1 += vb * wv[no][0]; zf1 += vb * wv[no][1];
                    zg1 += vb * wv[no][2]; zo1 += vb * wv[no][3];
                }
                int ci = mf * 4 + no * 2;
                float cA = sigf(zf0) * cst[ci]     + sigf(zi0) * tanhap(zg0);
                float cB = sigf(zf1) * cst[ci + 1] + sigf(zi1) * tanhap(zg1);
                cst[ci] = cA; cst[ci + 1] = cB;
                float hA = sigf(zo0) * tanhap(cA);
                float hB = sigf(zo1) * tanhap(cB);
                hout[(size_t)(b0 + r0) * HHID + ug[no]]     = __float2half(hA);
                hout[(size_t)(b0 + r0 + 8) * HHID + ug[no]] = __float2half(hB);
                if (do_head) {
                    pv[mf * 2]     += hA * hw[no];
                    pv[mf * 2 + 1] += hB * hw[no];
                }
            }
        }
    }
    if (do_head) {
#pragma unroll
        for (int q = 0; q < 4; q++) {
            float sv = pv[q] + __shfl_xor_sync(FULL, pv[q], 1);
            sv += __shfl_xor_sync(FULL, sv, 2);
            if (tig == 0) {
                int row = wm + (q >> 1) * 16 + grp + (q & 1) * 8;
                g_part2[(size_t)(b0 + row) * 64 + slot] = sv;
            }
        }
    }
}

__global__ void __launch_bounds__(NTHR, 1)
lstm_persistent_kernel(const float* __restrict__ x,
                       const float* __restrict__ eWih0, const float* __restrict__ eWhh0,
                       const float* __restrict__ eb0,
                       const float* __restrict__ eWih1, const float* __restrict__ eWhh1,
                       const float* __restrict__ eb1,
                       const float* __restrict__ dWih0, const float* __restrict__ dWhh0,
                       const float* __restrict__ db0,
                       const float* __restrict__ dWih1, const float* __restrict__ dWhh1,
                       const float* __restrict__ db1,
                       const float* __restrict__ headW, const float* __restrict__ headb,
                       float* __restrict__ out) {
    extern __shared__ __align__(1024) char smem[];
    uint32_t sb;
    asm("{ .reg .u64 t; cvta.to.shared.u64 t, %1; cvt.u32.u64 %0, t; }"
        : "=r"(sb) : "l"(smem));
    const uint32_t ws0 = sb, ws1 = sb + WS_BYTES, ws2 = sb + 2 * WS_BYTES;
    const uint32_t ring = sb + RING_OFF;
    float* dins = (float*)(smem + DINS_OFF);
    const uint32_t mb = sb + MBAR_OFF;      // pairbar j: full=mb+16j, empty=mb+16j+8

    const int tid  = threadIdx.x;
    const int lane = tid & 31, warp = tid >> 5;
    const int cta  = blockIdx.x;
    const int mbk  = cta >> 5, nc = cta & 31;
    const int b0   = mbk * 128, n0 = nc * 64;
    const int wm   = ((warp & 7) >> 1) * 32, wn = (warp & 1) * 32;
    const int grp  = lane >> 2, tig = lane & 3;
    const int slot = nc * 2 + (warp & 1);

    int ug[2];
    ug[0] = nc * 16 + (wn >> 2) + ((tig & 1) ? 2 : 0) + (tig >> 1);
    ug[1] = ug[0] + 4;

    /* group-gen snapshot BEFORE global init barrier -> launch-idempotent gating */
    const unsigned gen0 = g_gen4[mbk];

    /* ---- init ---- */
    if (tid == 0) {
#pragma unroll
        for (int s = 0; s < 2; s++) {        // TWO pair-barriers
            mb_init(mb + s * 16, 32);        // full: 32 producer-lane arrivals (noinc)
            mb_init(mb + s * 16 + 8, 8);     // empty: 8 consumer-warp arrivals
        }
    }
    load_w1(smem, eWhh0, 0, n0, tid, NTHR);
    load_w1(smem, eWih1, WS_BYTES, n0, tid, NTHR);
    load_w1(smem, eWhh1, 2 * WS_BYTES, n0, tid, NTHR);
    {
        int gtid = cta * NTHR + tid;
        for (int i = gtid; i < BB * HHID; i += NCTA * NTHR)
            g_h1[1][i] = __float2half(0.f);   // h1(-1) = 0
    }
    float bv0[2][4], wv0[2][4], bv1[2][4], hw[2];
    load_gv(bv0, eb0, ug[0], ug[1]);
    load_gv(wv0, eWih0, ug[0], ug[1]);
    load_gv(bv1, eb1, ug[0], ug[1]);
    hw[0] = headW[ug[0]]; hw[1] = headW[ug[1]];
    const float hb = headb[0];
    float c0st[8], c1st[8];
#pragma unroll
    for (int i = 0; i < 8; i++) { c0st[i] = 0.f; c1st[i] = 0.f; }

    /* prologue: A(0) with zero recurrent gates (consumers only) */
    if (warp < 8) {
        if (tid < 128) dins[tid] = x[(size_t)(b0 + tid) * TT + 0];
        CBAR();
        float accZ[2][4][4];
#pragma unroll
        for (int a = 0; a < 2; a++)
#pragma unroll
            for (int b = 0; b < 4; b++)
#pragma unroll
                for (int c = 0; c < 4; c++) accZ[a][b][c] = 0.f;
        pointwise_frag(accZ, c0st, bv0, wv0, true, dins, wm, grp, tig,
                       g_h0[0], b0, ug, false, hw, slot);
    }
    grid_bar_full();   // global: publishes h0(0), zeros, mbarrier inits

    if (warp >= 8) {
        /* ============ PRODUCER WARPS (8, 9): one pair-slot each ============ */
        const int pidx = warp - 8;          // handles pairs with (pp & 1) == pidx
        const uint32_t mybar = mb + pidx * 16;
        const int bufA = pidx * 2, bufB = pidx * 2 + 1;
        int ph = 1;                          // empty-wait parity (first passes)
#pragma unroll 1
        for (int s = 0; s < TT + HOR; s++) {
            unsigned need = (unsigned)((s <= TT) ? s : (TT + 2 * (s - TT)));
            while ((unsigned)(g_gen4[mbk] - gen0) < need) { }
            __threadfence();
            const __half* h0s = g_h0[s & 1];
            const __half* h1p = g_h1[(s & 1) ^ 1];
#pragma unroll 1
            for (int pp = pidx; pp < 16; pp += 2) {   // 8 pairs per producer
                mb_wait(mybar + 8, (uint32_t)ph);
                int c0 = 2 * pp, c1 = 2 * pp + 1;
                if (pp < 8) {
                    p_stage_na(ring, bufA, h0s, b0, c0 * 32, lane);
                    p_stage_na(ring, bufB, h0s, b0, c1 * 32, lane);
                } else {
                    p_stage_na(ring, bufA, h1p, b0, (c0 - 16) * 32, lane);
                    p_stage_na(ring, bufB, h1p, b0, (c1 - 16) * 32, lane);
                }
                CPA_ARRIVE(mybar);
                ph ^= 1;
            }
        }
        return;
    }

    /* =================== CONSUMER WARPS (0..7) =================== */
    int cs = 0, cph = 0;                     // pair cursor over 2 pair-barriers
#pragma unroll 1
    for (int s = 0; s < TT + HOR; s++) {
        /* weight switches (smem is CTA-private; CBARs fence all consumer reads) */
        if (s == TT - 1) {
            CBAR();
            load_w1(smem, dWhh0, 0, n0, tid, NCON);
            load_gv(bv0, db0, ug[0], ug[1]);
            load_gv(wv0, dWih0, ug[0], ug[1]);
            CBAR();
        }
        if (s == TT) {
            CBAR();
            load_w1(smem, dWih1, WS_BYTES, n0, tid, NCON);
            load_w1(smem, dWhh1, 2 * WS_BYTES, n0, tid, NCON);
            load_gv(bv1, db1, ug[0], ug[1]);
            CBAR();
        }

        float accA[2][4][4], accB[2][4][4];
#pragma unroll
        for (int a = 0; a < 2; a++)
#pragma unroll
            for (int b = 0; b < 4; b++)
#pragma unroll
                for (int c = 0; c < 4; c++) { accA[a][b][c] = 0.f; accB[a][b][c] = 0.f; }

#pragma unroll 1
        for (int pp = 0; pp < 8; pp++) {              // h0(s): dual MMA, pair-wise
            mb_wait(mb + cs * 16, (uint32_t)cph);
            chunk_dual32(accA, accB, ring + (cs * 2) * STAGE_BYTES, ws0, ws1,
                         2 * pp, wm, wn, lane);
            chunk_dual32(accA, accB, ring + (cs * 2 + 1) * STAGE_BYTES, ws0, ws1,
                         2 * pp + 1, wm, wn, lane);
            if (lane == 0) mb_arrive(mb + cs * 16 + 8);
            if (++cs == 2) { cs = 0; cph ^= 1; }
        }
#pragma unroll 1
        for (int pp = 0; pp < 8; pp++) {              // h1(s-1): single MMA, pair-wise
            mb_wait(mb + cs * 16, (uint32_t)cph);
            chunk_one32(accB, ring + (cs * 2) * STAGE_BYTES, ws2,
                        2 * pp, wm, wn, lane);
            chunk_one32(accB, ring + (cs * 2 + 1) * STAGE_BYTES, ws2,
                        2 * pp + 1, wm, wn, lane);
            if (lane == 0) mb_arrive(mb + cs * 16 + 8);
            if (++cs == 2) { cs = 0; cph ^= 1; }
        }

        const bool dec = (s >= TT);
        /* pointwise B(s): h1(s), c1, head partials in decoder */
        pointwise_frag(accB, c1st, bv1, wv0, false, dins, wm, grp, tig,
                       g_h1[s & 1], b0, ug, dec, hw, slot);

        if (dec) {
            group_bar_c(tid, mbk);                    // mid bar: publish g_part2
            if (tid < 128) {
                float v = hb;
                const float4* gp = (const float4*)(g_part2 + (size_t)(b0 + tid) * 64);
#pragma unroll
                for (int q = 0; q < 16; q++) {
                    float4 t = __ldcg(&gp[q]);
                    v += t.x + t.y + t.z + t.w;
                }
                if (nc == 0) out[(size_t)(b0 + tid) * HOR + (s - TT)] = v;
                dins[tid] = v;
            }
            CBAR();
        } else {
            int nx = (s + 1 < TT) ? (s + 1) : (TT - 1);
            if (tid < 128) dins[tid] = x[(size_t)(b0 + tid) * TT + nx];
            CBAR();
        }

        if (s + 1 < TT + HOR) {
            /* pointwise A(s+1): h0(s+1), c0 */
            pointwise_frag(accA, c0st, bv0, wv0, true, dins, wm, grp, tig,
                           g_h0[(s + 1) & 1], b0, ug, false, hw, slot);
            group_bar_c(tid, mbk);                    // end bar: publish h0(s+1), h1(s)
        }
    }
}

extern "C" void kernel_launch(void* const* d_in, const int* in_sizes, int n_in,
                              void* d_out, int out_size) {
    cudaFuncSetAttribute(lstm_persistent_kernel,
                         cudaFuncAttributeMaxDynamicSharedMemorySize, SMEM_BYTES);
    lstm_persistent_kernel<<<NCTA, NTHR, SMEM_BYTES>>>(
        (const float*)d_in[0],
        (const float*)d_in[1], (const float*)d_in[2], (const float*)d_in[3],
        (const float*)d_in[4], (const float*)d_in[5], (const float*)d_in[6],
        (const float*)d_in[7], (const float*)d_in[8], (const float*)d_in[9],
        (const float*)d_in[10], (const float*)d_in[11], (const float*)d_in[12],
        (const float*)d_in[13], (const float*)d_in[14],
        (float*)d_out);
}

// round 16
// speedup vs baseline: 1.8533x; 1.0139x over previous
#include <cuda_runtime.h>
#include <cuda_fp16.h>
#include <stdint.h>

#define BB   512
#define TT   256
#define HHID 512
#define HOR  64
#define NCTA 128
#define NGRP 32                         /* CTAs per independent batch group */
#define NTHR 320                        /* 8 consumer warps + 2 producer warps */
#define NCON 256
#define WS_BYTES    65536               /* one matrix slice: 64 rows x 512 halves */
#define RING_OFF    (3 * WS_BYTES)      /* 196608 */
#define STAGE_BYTES 4096                /* K=32 chunk of M=64: 64 rows folded to 32x128B */
#define RING_BYTES  16384               /* 4 buffers per ring */
#define DINS_OFF    (RING_OFF + 2 * RING_BYTES)       /* 229376 */
#define MBAR_OFF    (DINS_OFF + 512)                  /* 229888 */
#define SMEM_BYTES  (MBAR_OFF + 128)                  /* 230016 */

__device__ __align__(128) __half g_h0[2][BB * HHID];
__device__ __align__(128) __half g_h1[2][BB * HHID];
__device__ float  g_part2[BB * 64];     /* [row][slot], slot = nc*2 + (warp&1) */
__device__ unsigned g_count0 = 0u;              /* init barrier (global) */
__device__ volatile unsigned g_gen0v = 0u;
__device__ unsigned g_count4[4] = {0u, 0u, 0u, 0u};   /* per-group barriers */
__device__ volatile unsigned g_gen4[4] = {0u, 0u, 0u, 0u};

/* ---------- barriers ---------- */
__device__ __forceinline__ void grid_bar_full() {      // ALL CTAs, init only
    __syncthreads();
    __threadfence();
    if (threadIdx.x == 0) {
        unsigned g = g_gen0v;
        if (atomicAdd(&g_count0, 1u) == NCTA - 1) {
            g_count0 = 0u; __threadfence(); g_gen0v = g + 1u;
        } else { while (g_gen0v == g) { } }
        __threadfence();
    }
    __syncthreads();
}
#define CBAR() asm volatile("bar.sync 1, %0;" :: "n"(NCON) : "memory")
__device__ __forceinline__ void group_bar_c(int tid, int grp_id) {  // consumers, own group
    CBAR();
    __threadfence();
    if (tid == 0) {
        unsigned g = g_gen4[grp_id];
        if (atomicAdd(&g_count4[grp_id], 1u) == NGRP - 1) {
            g_count4[grp_id] = 0u; __threadfence(); g_gen4[grp_id] = g + 1u;
        } else { while (g_gen4[grp_id] == g) { } }
        __threadfence();
    }
    CBAR();
}

/* ---------- mbarrier ---------- */
__device__ __forceinline__ void mb_init(uint32_t a, uint32_t cnt) {
    asm volatile("mbarrier.init.shared.b64 [%0], %1;" :: "r"(a), "r"(cnt) : "memory");
}
__device__ __forceinline__ void mb_arrive(uint32_t a) {
    asm volatile("mbarrier.arrive.shared.b64 _, [%0];" :: "r"(a) : "memory");
}
__device__ __forceinline__ void mb_wait(uint32_t a, uint32_t par) {
    asm volatile(
        "{\n\t.reg .pred P;\n\t"
        "LW_%=:\n\t"
        "mbarrier.try_wait.parity.acquire.cta.shared::cta.b64 P, [%0], %1, 0x989680;\n\t"
        "@P bra.uni LD_%=;\n\t"
        "bra.uni LW_%=;\n\t"
        "LD_%=:\n\t}"
        :: "r"(a), "r"(par) : "memory");
}

/* ---------- async copy / mma ---------- */
__device__ __forceinline__ void cpa16(uint32_t dst, const void* src) {
    asm volatile("cp.async.cg.shared.global [%0], [%1], 16;\n" :: "r"(dst), "l"(src));
}
__device__ __forceinline__ void ldsm4(uint32_t* r, uint32_t a) {
    asm volatile("ldmatrix.sync.aligned.m8n8.x4.shared.b16 {%0,%1,%2,%3}, [%4];\n"
                 : "=r"(r[0]), "=r"(r[1]), "=r"(r[2]), "=r"(r[3]) : "r"(a));
}
#define MMA(d, A, B0, B1)                                                      \
    asm volatile("mma.sync.aligned.m16n8k16.row.col.f32.f16.f16.f32 "          \
                 "{%0,%1,%2,%3},{%4,%5,%6,%7},{%8,%9},{%0,%1,%2,%3};"          \
                 : "+f"(d[0]), "+f"(d[1]), "+f"(d[2]), "+f"(d[3])              \
                 : "r"(A[0]), "r"(A[1]), "r"(A[2]), "r"(A[3]), "r"(B0), "r"(B1))

/* producer: stage one K=32 chunk of M=64 rows (64 rows x 32 halves -> 32x128B fold) */
__device__ __forceinline__ void p_stage_na(uint32_t ringg, int buf, const __half* hsrc,
                                           int b0g, int kc, int lane) {
    uint32_t base = ringg + buf * STAGE_BYTES;
#pragma unroll
    for (int u = 0; u < 8; u++) {
        int i = lane + u * 32;              // 0..255 16B blocks
        int br = i >> 2, cb4 = i & 3;       // br 0..63
        int phys = (cb4 + ((br >> 5) << 2)) ^ (br & 7);
        cpa16(base + (br & 31) * 128 + (phys << 4),
              hsrc + (size_t)(b0g + br) * HHID + kc + cb4 * 8);
    }
}
#define CPA_ARRIVE(bar) \
    asm volatile("cp.async.mbarrier.arrive.noinc.shared.b64 [%0];" :: "r"(bar) : "memory")

/* dual chunk, 32x32 tile over an M=64 stage: accA += A x W0^T, accB += A x W1^T */
__device__ __forceinline__ void chunk_dual32(float aA[2][4][4], float aB[2][4][4],
                                             uint32_t Ast, uint32_t W0, uint32_t W1,
                                             int chk, int wm, int wn, int lane) {
    const int a_row = lane & 15, akc = lane >> 4;
    const int b_row = (lane & 7) + ((lane >> 4) << 3), bkc = (lane >> 3) & 1;
    const int R0 = wn + b_row, R1 = R0 + 16;
    const int R07 = R0 & 7, R17 = R1 & 7;
    const uint32_t W0r0 = W0 + R0 * 1024, W0r1 = W0 + R1 * 1024;
    const uint32_t W1r0 = W1 + R0 * 1024, W1r1 = W1 + R1 * 1024;
    const int lr0 = wm + a_row, lr1 = lr0 + 16;        // 0..63 within stage
    const uint32_t Ar0 = Ast + (lr0 & 31) * 128, Ar1 = Ast + (lr1 & 31) * 128;
    const int hb0 = (lr0 >> 5) << 2, hb1 = (lr1 >> 5) << 2;
    const int l07 = lr0 & 7, l17 = lr1 & 7;
#pragma unroll
    for (int kk = 0; kk < 32; kk += 16) {
        int k8 = kk >> 3;
        int cb = chk * 4 + k8 + bkc;
        uint32_t Ca[4], Cb[4], Ba[4], Bb[4], A0[4], A1[4];
        ldsm4(Ca, W0r0 + ((cb ^ R07) << 4));
        ldsm4(Cb, W0r1 + ((cb ^ R17) << 4));
        ldsm4(Ba, W1r0 + ((cb ^ R07) << 4));
        ldsm4(Bb, W1r1 + ((cb ^ R17) << 4));
        ldsm4(A0, Ar0 + ((((k8 + akc + hb0) ^ l07)) << 4));
        ldsm4(A1, Ar1 + ((((k8 + akc + hb1) ^ l17)) << 4));
        MMA(aB[0][0], A0, Ba[0], Ba[1]);
        MMA(aB[0][1], A0, Ba[2], Ba[3]);
        MMA(aB[0][2], A0, Bb[0], Bb[1]);
        MMA(aB[0][3], A0, Bb[2], Bb[3]);
        MMA(aB[1][0], A1, Ba[0], Ba[1]);
        MMA(aB[1][1], A1, Ba[2], Ba[3]);
        MMA(aB[1][2], A1, Bb[0], Bb[1]);
        MMA(aB[1][3], A1, Bb[2], Bb[3]);
        MMA(aA[0][0], A0, Ca[0], Ca[1]);
        MMA(aA[0][1], A0, Ca[2], Ca[3]);
        MMA(aA[0][2], A0, Cb[0], Cb[1]);
        MMA(aA[0][3], A0, Cb[2], Cb[3]);
        MMA(aA[1][0], A1, Ca[0], Ca[1]);
        MMA(aA[1][1], A1, Ca[2], Ca[3]);
        MMA(aA[1][2], A1, Cb[0], Cb[1]);
        MMA(aA[1][3], A1, Cb[2], Cb[3]);
    }
}

/* single chunk, 32x32 tile over an M=64 stage: accB += A x W^T */
__device__ __forceinline__ void chunk_one32(float aB[2][4][4],
                                            uint32_t Ast, uint32_t W1,
                                            int chk, int wm, int wn, int lane) {
    const int a_row = lane & 15, akc = lane >> 4;
    const int b_row = (lane & 7) + ((lane >> 4) << 3), bkc = (lane >> 3) & 1;
    const int R0 = wn + b_row, R1 = R0 + 16;
    const int R07 = R0 & 7, R17 = R1 & 7;
    const uint32_t W1r0 = W1 + R0 * 1024, W1r1 = W1 + R1 * 1024;
    const int lr0 = wm + a_row, lr1 = lr0 + 16;
    const uint32_t Ar0 = Ast + (lr0 & 31) * 128, Ar1 = Ast + (lr1 & 31) * 128;
    const int hb0 = (lr0 >> 5) << 2, hb1 = (lr1 >> 5) << 2;
    const int l07 = lr0 & 7, l17 = lr1 & 7;
#pragma unroll
    for (int kk = 0; kk < 32; kk += 16) {
        int k8 = kk >> 3;
        int cb = chk * 4 + k8 + bkc;
        uint32_t Ba[4], Bb[4], A0[4], A1[4];
        ldsm4(Ba, W1r0 + ((cb ^ R07) << 4));
        ldsm4(Bb, W1r1 + ((cb ^ R17) << 4));
        ldsm4(A0, Ar0 + ((((k8 + akc + hb0) ^ l07)) << 4));
        ldsm4(A1, Ar1 + ((((k8 + akc + hb1) ^ l17)) << 4));
        MMA(aB[0][0], A0, Ba[0], Ba[1]);
        MMA(aB[0][1], A0, Ba[2], Ba[3]);
        MMA(aB[0][2], A0, Bb[0], Bb[1]);
        MMA(aB[0][3], A0, Bb[2], Bb[3]);
        MMA(aB[1][0], A1, Ba[0], Ba[1]);
        MMA(aB[1][1], A1, Ba[2], Ba[3]);
        MMA(aB[1][2], A1, Bb[0], Bb[1]);
        MMA(aB[1][3], A1, Bb[2], Bb[3]);
    }
}

/* convert ONE weight matrix 64-row slice fp32 -> fp16 into swizzled smem slot */
__device__ void load_w1(char* smem, const float* W, int moff, int n0, int tid, int nthr) {
    for (int i = tid; i < 64 * 512; i += nthr) {
        int r = i >> 9, k = i & 511;
        int pr = n0 + r, j = pr >> 2, g = pr & 3;
        float v = W[(size_t)(g * 512 + j) * HHID + k];
        int ck = k >> 3;
        int off = moff + r * 1024 + (((ck ^ (r & 7)) << 4)) + (k & 7) * 2;
        *(__half*)(smem + off) = __float2half(v);
    }
}

__device__ __forceinline__ void load_gv(float d[2][4], const float* b, int u0, int u1) {
    d[0][0] = b[u0]; d[0][1] = b[512 + u0]; d[0][2] = b[1024 + u0]; d[0][3] = b[1536 + u0];
    d[1][0] = b[u1]; d[1][1] = b[512 + u1]; d[1][2] = b[1024 + u1]; d[1][3] = b[1536 + u1];
}

/* HW tanh (sm_75+): max abs err ~6e-4, within budget (verified R11+) */
__device__ __forceinline__ float tanhap(float z) {
    float r;
    asm("tanh.approx.f32 %0, %1;" : "=f"(r) : "f"(z));
    return r;
}
__device__ __forceinline__ float sigf(float z) { return 0.5f * tanhap(0.5f * z) + 0.5f; }

/* balanced in-register LSTM pointwise for 32x32 tiles (verified layout) */
__device__ __forceinline__ void pointwise_frag(
    const float acc[2][4][4], float* cst /*[8]*/,
    const float bv[2][4], const float wv[2][4], bool use_w,
    const float* dins, int wm, int grp, int tig,
    __half* hout, int b0, const int* ug,
    bool do_head, const float* hw, int slot) {
    const unsigned FULL = 0xFFFFFFFFu;
    float pv[4] = {0.f, 0.f, 0.f, 0.f};
#pragma unroll
    for (int mf = 0; mf < 2; mf++) {
        int r0 = wm + mf * 16 + grp;
        float va = use_w ? dins[r0] : 0.f;
        float vb = use_w ? dins[r0 + 8] : 0.f;
#pragma unroll
        for (int nf = 0; nf < 4; nf++) {
            float e0 = __shfl_xor_sync(FULL, acc[mf][nf][0], 1);
            float e1 = __shfl_xor_sync(FULL, acc[mf][nf][1], 1);
            float e2 = __shfl_xor_sync(FULL, acc[mf][nf][2], 1);
            float e3 = __shfl_xor_sync(FULL, acc[mf][nf][3], 1);
            if (((nf ^ tig) & 1) == 0) {
                int no = nf >> 1;
                float zi0, zf0, zg0, zo0, zi1, zf1, zg1, zo1;
                if ((tig & 1) == 0) {
                    zi0 = acc[mf][nf][0]; zf0 = acc[mf][nf][1]; zg0 = e0; zo0 = e1;
                    zi1 = acc[mf][nf][2]; zf1 = acc[mf][nf][3]; zg1 = e2; zo1 = e3;
                } else {
                    zg0 = acc[mf][nf][0]; zo0 = acc[mf][nf][1]; zi0 = e0; zf0 = e1;
                    zg1 = acc[mf][nf][2]; zo1 = acc[mf][nf][3]; zi1 = e2; zf1 = e3;
                }
                zi0 += bv[no][0]; zf0 += bv[no][1]; zg0 += bv[no][2]; zo0 += bv[no][3];
                zi1 += bv[no][0]; zf1 += bv[no][1]; zg1 += bv[no][2]; zo1 += bv[no][3];
                if (use_w) {
                    zi0 += va * wv[no][0]; zf0 += va * wv[no][1];
                    zg0 += va * wv[no][2]; zo0 += va * wv[no][3];
                    zi1 += vb * wv[no][0]; zf1 += vb * wv[no][1];
                    zg1 += vb * wv[no][2]; zo1 += vb * wv[no][3];
                }
                int ci = mf * 4 + no * 2;
                float cA = sigf(zf0) * cst[ci]     + sigf(zi0) * tanhap(zg0);
                float cB = sigf(zf1) * cst[ci + 1] + sigf(zi1) * tanhap(zg1);
                cst[ci] = cA; cst[ci + 1] = cB;
                float hA = sigf(zo0) * tanhap(cA);
                float hB = sigf(zo1) * tanhap(cB);
                hout[(size_t)(b0 + r0) * HHID + ug[no]]     = __float2half(hA);
                hout[(size_t)(b0 + r0 + 8) * HHID + ug[no]] = __float2half(hB);
                if (do_head) {
                    pv[mf * 2]     += hA * hw[no];
                    pv[mf * 2 + 1] += hB * hw[no];
                }
            }
        }
    }
    if (do_head) {
#pragma unroll
        for (int q = 0; q < 4; q++) {
            float sv = pv[q] + __shfl_xor_sync(FULL, pv[q], 1);
            sv += __shfl_xor_sync(FULL, sv, 2);
            if (tig == 0) {
                int row = wm + (q >> 1) * 16 + grp + (q & 1) * 8;
                g_part2[(size_t)(b0 + row) * 64 + slot] = sv;
            }
        }
    }
}

__global__ void __launch_bounds__(NTHR, 1)
lstm_persistent_kernel(const float* __restrict__ x,
                       const float* __restrict__ eWih0, const float* __restrict__ eWhh0,
                       const float* __restrict__ eb0,
                       const float* __restrict__ eWih1, const float* __restrict__ eWhh1,
                       const float* __restrict__ eb1,
                       const float* __restrict__ dWih0, const float* __restrict__ dWhh0,
                       const float* __restrict__ db0,
                       const float* __restrict__ dWih1, const float* __restrict__ dWhh1,
                       const float* __restrict__ db1,
                       const float* __restrict__ headW, const float* __restrict__ headb,
                       float* __restrict__ out) {
    extern __shared__ __align__(1024) char smem[];
    uint32_t sb;
    asm("{ .reg .u64 t; cvta.to.shared.u64 t, %1; cvt.u32.u64 %0, t; }"
        : "=r"(sb) : "l"(smem));
    const uint32_t ws0 = sb, ws1 = sb + WS_BYTES, ws2 = sb + 2 * WS_BYTES;
    const uint32_t ring = sb + RING_OFF;
    float* dins = (float*)(smem + DINS_OFF);
    const uint32_t mb = sb + MBAR_OFF;  // ring g pair j: full=mb+(g*2+j)*16, empty=+8

    const int tid  = threadIdx.x;
    const int lane = tid & 31, warp = tid >> 5;
    const int cta  = blockIdx.x;
    const int mbk  = cta >> 5, nc = cta & 31;
    const int b0   = mbk * 128, n0 = nc * 64;
    /* consumer mapping: group (ring) = warp>>2, wm within ring, wn */
    const int cg   = (warp & 7) >> 2;
    const int wm   = ((warp >> 1) & 1) * 32;
    const int wn   = (warp & 1) * 32;
    const int wmp  = cg * 64 + wm;            // rows for pointwise/dins/head
    const uint32_t ringg_c = ring + cg * RING_BYTES;
    const uint32_t mbg_c   = mb + cg * 32;
    const int grp  = lane >> 2, tig = lane & 3;
    const int slot = nc * 2 + (warp & 1);

    int ug[2];
    ug[0] = nc * 16 + (wn >> 2) + ((tig & 1) ? 2 : 0) + (tig >> 1);
    ug[1] = ug[0] + 4;

    /* group-gen snapshot BEFORE global init barrier -> launch-idempotent gating */
    const unsigned gen0 = g_gen4[mbk];

    /* ---- init ---- */
    if (tid == 0) {
#pragma unroll
        for (int j = 0; j < 4; j++) {        // 2 rings x 2 pair-barriers
            mb_init(mb + j * 16, 32);        // full: 32 producer-lane arrivals (noinc)
            mb_init(mb + j * 16 + 8, 4);     // empty: 4 consumer-warp arrivals
        }
    }
    load_w1(smem, eWhh0, 0, n0, tid, NTHR);
    load_w1(smem, eWih1, WS_BYTES, n0, tid, NTHR);
    load_w1(smem, eWhh1, 2 * WS_BYTES, n0, tid, NTHR);
    {
        int gtid = cta * NTHR + tid;
        for (int i = gtid; i < BB * HHID; i += NCTA * NTHR)
            g_h1[1][i] = __float2half(0.f);   // h1(-1) = 0
    }
    float bv0[2][4], wv0[2][4], bv1[2][4], hw[2];
    load_gv(bv0, eb0, ug[0], ug[1]);
    load_gv(wv0, eWih0, ug[0], ug[1]);
    load_gv(bv1, eb1, ug[0], ug[1]);
    hw[0] = headW[ug[0]]; hw[1] = headW[ug[1]];
    const float hb = headb[0];
    float c0st[8], c1st[8];
#pragma unroll
    for (int i = 0; i < 8; i++) { c0st[i] = 0.f; c1st[i] = 0.f; }

    /* prologue: A(0) with zero recurrent gates (consumers only) */
    if (warp < 8) {
        if (tid < 128) dins[tid] = x[(size_t)(b0 + tid) * TT + 0];
        CBAR();
        float accZ[2][4][4];
#pragma unroll
        for (int a = 0; a < 2; a++)
#pragma unroll
            for (int b = 0; b < 4; b++)
#pragma unroll
                for (int c = 0; c < 4; c++) accZ[a][b][c] = 0.f;
        pointwise_frag(accZ, c0st, bv0, wv0, true, dins, wmp, grp, tig,
                       g_h0[0], b0, ug, false, hw, slot);
    }
    grid_bar_full();   // global: publishes h0(0), zeros, mbarrier inits

    if (warp >= 8) {
        /* ===== PRODUCER WARPS (8, 9): one ring / one M-half each ===== */
        const int pg = warp - 8;
        const uint32_t ringg = ring + pg * RING_BYTES;
        const uint32_t mbg = mb + pg * 32;
        const int b0g = b0 + pg * 64;
        int pj = 0;
        int pph[2] = {1, 1};
#pragma unroll 1
        for (int s = 0; s < TT + HOR; s++) {
            unsigned need = (unsigned)((s <= TT) ? s : (TT + 2 * (s - TT)));
            while ((unsigned)(g_gen4[mbk] - gen0) < need) { }
            __threadfence();
            const __half* h0s = g_h0[s & 1];
            const __half* h1p = g_h1[(s & 1) ^ 1];
#pragma unroll 1
            for (int pp = 0; pp < 16; pp++) {   // 16 pairs (K=64 each) per step
                mb_wait(mbg + pj * 16 + 8, (uint32_t)pph[pj]);
                if (pp < 8) {
                    p_stage_na(ringg, pj * 2,     h0s, b0g, 64 * pp, lane);
                    p_stage_na(ringg, pj * 2 + 1, h0s, b0g, 64 * pp + 32, lane);
                } else {
                    int q = pp - 8;
                    p_stage_na(ringg, pj * 2,     h1p, b0g, 64 * q, lane);
                    p_stage_na(ringg, pj * 2 + 1, h1p, b0g, 64 * q + 32, lane);
                }
                CPA_ARRIVE(mbg + pj * 16);
                pph[pj] ^= 1;
                pj ^= 1;
            }
        }
        return;
    }

    /* =================== CONSUMER WARPS (0..7) =================== */
    int cs = 0, cph = 0;                     // pair cursor within this ring
#pragma unroll 1
    for (int s = 0; s < TT + HOR; s++) {
        /* weight switches (smem is CTA-private; CBARs fence all consumer reads) */
        if (s == TT - 1) {
            CBAR();
            load_w1(smem, dWhh0, 0, n0, tid, NCON);
            load_gv(bv0, db0, ug[0], ug[1]);
            load_gv(wv0, dWih0, ug[0], ug[1]);
            CBAR();
        }
        if (s == TT) {
            CBAR();
            load_w1(smem, dWih1, WS_BYTES, n0, tid, NCON);
            load_w1(smem, dWhh1, 2 * WS_BYTES, n0, tid, NCON);
            load_gv(bv1, db1, ug[0], ug[1]);
            CBAR();
        }

        float accA[2][4][4], accB[2][4][4];
#pragma unroll
        for (int a = 0; a < 2; a++)
#pragma unroll
            for (int b = 0; b < 4; b++)
#pragma unroll
                for (int c = 0; c < 4; c++) { accA[a][b][c] = 0.f; accB[a][b][c] = 0.f; }

#pragma unroll 1
        for (int pp = 0; pp < 8; pp++) {              // h0(s): dual MMA, pair-wise
            mb_wait(mbg_c + cs * 16, (uint32_t)cph);
            chunk_dual32(accA, accB, ringg_c + (cs * 2) * STAGE_BYTES, ws0, ws1,
                         2 * pp, wm, wn, lane);
            chunk_dual32(accA, accB, ringg_c + (cs * 2 + 1) * STAGE_BYTES, ws0, ws1,
                         2 * pp + 1, wm, wn, lane);
            if (lane == 0) mb_arrive(mbg_c + cs * 16 + 8);
            if (++cs == 2) { cs = 0; cph ^= 1; }
        }
#pragma unroll 1
        for (int pp = 0; pp < 8; pp++) {              // h1(s-1): single MMA, pair-wise
            mb_wait(mbg_c + cs * 16, (uint32_t)cph);
            chunk_one32(accB, ringg_c + (cs * 2) * STAGE_BYTES, ws2,
                        2 * pp, wm, wn, lane);
            chunk_one32(accB, ringg_c + (cs * 2 + 1) * STAGE_BYTES, ws2,
                        2 * pp + 1, wm, wn, lane);
            if (lane == 0) mb_arrive(mbg_c + cs * 16 + 8);
            if (++cs == 2) { cs = 0; cph ^= 1; }
        }

        const bool dec = (s >= TT);
        /* pointwise B(s): h1(s), c1, head partials in decoder */
        pointwise_frag(accB, c1st, bv1, wv0, false, dins, wmp, grp, tig,
                       g_h1[s & 1], b0, ug, dec, hw, slot);

        if (dec) {
            group_bar_c(tid, mbk);                    // mid bar: publish g_part2
            if (tid < 128) {
                float v = hb;
                const float4* gp = (const float4*)(g_part2 + (size_t)(b0 + tid) * 64);
#pragma unroll
                for (int q = 0; q < 16; q++) {
                    float4 t = __ldcg(&gp[q]);
                    v += t.x + t.y + t.z + t.w;
                }
                if (nc == 0) out[(size_t)(b0 + tid) * HOR + (s - TT)] = v;
                dins[tid] = v;
            }
            CBAR();
        } else {
            int nx = (s + 1 < TT) ? (s + 1) : (TT - 1);
            if (tid < 128) dins[tid] = x[(size_t)(b0 + tid) * TT + nx];
            CBAR();
        }

        if (s + 1 < TT + HOR) {
            /* pointwise A(s+1): h0(s+1), c0 */
            pointwise_frag(accA, c0st, bv0, wv0, true, dins, wmp, grp, tig,
                           g_h0[(s + 1) & 1], b0, ug, false, hw, slot);
            group_bar_c(tid, mbk);                    // end bar: publish h0(s+1), h1(s)
        }
    }
}

extern "C" void kernel_launch(void* const* d_in, const int* in_sizes, int n_in,
                              void* d_out, int out_size) {
    cudaFuncSetAttribute(lstm_persistent_kernel,
                         cudaFuncAttributeMaxDynamicSharedMemorySize, SMEM_BYTES);
    lstm_persistent_kernel<<<NCTA, NTHR, SMEM_BYTES>>>(
        (const float*)d_in[0],
        (const float*)d_in[1], (const float*)d_in[2], (const float*)d_in[3],
        (const float*)d_in[4], (const float*)d_in[5], (const float*)d_in[6],
        (const float*)d_in[7], (const float*)d_in[8], (const float*)d_in[9],
        (const float*)d_in[10], (const float*)d_in[11], (const float*)d_in[12],
        (const float*)d_in[13], (const float*)d_in[14],
        (float*)d_out);
}